// round 9
// baseline (speedup 1.0000x reference)
#include <cuda_runtime.h>

#define DD   32
#define HH   128
#define WW   160
#define HWSZ (HH*WW)          // 20480
#define DHW  (DD*HWSZ)        // 655360
#define CIN_ 16
#define COUT_ 32

// ---------------- packed f32x2 helpers (Blackwell FFMA2 path) --------------
typedef unsigned long long u64t;

__device__ __forceinline__ u64t pack2(float a, float b) {
    u64t r;
    asm("mov.b64 %0, {%1, %2};" : "=l"(r) : "f"(a), "f"(b));
    return r;
}
__device__ __forceinline__ void fma2(u64t& d, u64t a, u64t b) {
    asm("fma.rn.f32x2 %0, %1, %2, %0;" : "+l"(d) : "l"(a), "l"(b));
}
__device__ __forceinline__ float2 unpack2(u64t v) {
    float2 r;
    asm("mov.b64 {%0, %1}, %2;" : "=f"(r.x), "=f"(r.y) : "l"(v));
    return r;
}

// ---------------- scratch (allocation-free: device globals) ----------------
__device__ float g_off[18 * DHW];        // clipped offsets, [j][d][h][w]
__device__ float g_t1 [COUT_ * DHW];     // deformable conv out (raw, pre-BN1)
__device__ float g_u  [COUT_ * DHW];     // conv3d(w2) out
__device__ float g_id [COUT_ * DHW];     // conv3d(wd) out
__device__ float g_s1sum[COUT_ * DD], g_s1sq[COUT_ * DD];
__device__ float g_s2sum[COUT_], g_s2sq[COUT_], g_sdsum[COUT_], g_sdsq[COUT_];
__device__ float g_a1[COUT_ * DD], g_b1f[COUT_ * DD];
__device__ float g_a2[COUT_], g_b2f[COUT_], g_ad[COUT_], g_bdf[COUT_];
// pre-transposed weights (exact smem layout -> coalesced float4 staging)
__device__ float g_w2t[8 * 3456];        // [chunk][(cl*27+t)*32 + o]
__device__ float g_wdt[4 * 3456];        // [chunk][(cl*27+t)*32 + o]
__device__ float g_wrt[4608];            // [(c*9+k)*32 + o]
__device__ float g_wot[2592];            // [(c*9+k)*18 + j]

// ---------------- kernel 0: zero the stat accumulators ---------------------
__global__ void zero_stats_kernel() {
    int i = blockIdx.x * blockDim.x + threadIdx.x;
    if (i < COUT_ * DD) { g_s1sum[i] = 0.f; g_s1sq[i] = 0.f; }
    if (i < COUT_)      { g_s2sum[i] = 0.f; g_s2sq[i] = 0.f;
                          g_sdsum[i] = 0.f; g_sdsq[i] = 0.f; }
}

// ---------------- kernel 0b: weight pre-transpose --------------------------
__global__ void prep_weights_kernel(const float* __restrict__ w2,
                                    const float* __restrict__ wd,
                                    const float* __restrict__ w_reg,
                                    const float* __restrict__ w_off) {
    int i = blockIdx.x * blockDim.x + threadIdx.x;
    if (i < 27648) {                       // w2
        int o = i & 31, r = i >> 5;
        g_w2t[i] = w2[(o * 32 + r / 27) * 27 + r % 27];
    }
    if (i < 13824) {                       // wd
        int o = i & 31, r = i >> 5;
        g_wdt[i] = wd[(o * 16 + r / 27) * 27 + r % 27];
    }
    if (i < 4608) {
        int o = i & 31, ck = i >> 5;
        g_wrt[i] = w_reg[o * 144 + ck];
    }
    if (i < 2592) {
        int j = i % 18, ck = i / 18;
        g_wot[i] = w_off[j * 144 + ck];
    }
}

// ---------------- kernel 1: offset conv2d, P=2 in y ------------------------
// block (32,8), grid (5,8,32): 32x16 output tile, thread owns rows ty, ty+8.
__global__ void __launch_bounds__(256) offset_kernel(const float* __restrict__ f) {
    extern __shared__ float sm[];
    float* sf  = sm;                 // 16 * 18 * 34 = 9792
    float* swo = sm + 9792;          // 2592  (total 12384 floats = 49536 B)

    const int tid  = threadIdx.y * 32 + threadIdx.x;
    const int warp = tid >> 5, lane = tid & 31;
    const int d = blockIdx.z, h0 = blockIdx.y * 16, w0 = blockIdx.x * 32;
    const int ty = threadIdx.y, tx = threadIdx.x;

    for (int i = tid; i < 648; i += 256)
        ((float4*)swo)[i] = ((const float4*)g_wot)[i];

    // stage 16 planes x 18 rows x cols[-1..32], warp-per-row
#pragma unroll
    for (int c = 0; c < 16; c++) {
        const float* rowbase = f + (size_t)c * DHW + d * HWSZ + w0;
        float* dstp = sf + c * 612;
        for (int r = warp; r < 18; r += 8) {
            int hh = h0 + r - 1;
            bool ok = (hh >= 0) && (hh < HH);
            const float* rp = rowbase + hh * WW;
            float* dst = dstp + r * 34;
            dst[1 + lane] = ok ? rp[lane] : 0.f;
            if (lane < 2) {
                int ww_ = lane ? 32 : -1;
                float e = 0.f;
                if (ok && (unsigned)(w0 + ww_) < (unsigned)WW) e = rp[ww_];
                dst[lane ? 33 : 0] = e;
            }
        }
    }
    __syncthreads();

    u64t offA[9], offB[9];
#pragma unroll
    for (int j = 0; j < 9; j++) { offA[j] = 0ull; offB[j] = 0ull; }

    for (int c = 0; c < 16; c++) {
#pragma unroll
        for (int ky = 0; ky < 3; ky++)
#pragma unroll
        for (int kx = 0; kx < 3; kx++) {
            float sA = sf[c * 612 + (ty + ky) * 34 + tx + kx];
            float sB = sf[c * 612 + (ty + 8 + ky) * 34 + tx + kx];
            u64t sA2 = pack2(sA, sA);
            u64t sB2 = pack2(sB, sB);
            const u64t* wp = (const u64t*)&swo[(c * 9 + ky * 3 + kx) * 18];
#pragma unroll
            for (int j = 0; j < 9; j++) {
                u64t t2 = wp[j];
                fma2(offA[j], sA2, t2);
                fma2(offB[j], sB2, t2);
            }
        }
    }
    const int pixA = d * HWSZ + (h0 + ty) * WW + (w0 + tx);
    const int pixB = pixA + 8 * WW;
#pragma unroll
    for (int j = 0; j < 9; j++) {
        float2 pA = unpack2(offA[j]);
        float2 pB = unpack2(offB[j]);
        g_off[(2 * j    ) * DHW + pixA] = fminf(1.f, fmaxf(-1.f, pA.x));
        g_off[(2 * j + 1) * DHW + pixA] = fminf(1.f, fmaxf(-1.f, pA.y));
        g_off[(2 * j    ) * DHW + pixB] = fminf(1.f, fmaxf(-1.f, pB.x));
        g_off[(2 * j + 1) * DHW + pixB] = fminf(1.f, fmaxf(-1.f, pB.y));
    }
}

// ---------------- bilinear geometry helper ---------------------------------
__device__ __forceinline__ void bgeo(int h, int w, int ki, int kj,
                                     float dy, float dx,
                                     float& w00, float& w01, float& w10, float& w11,
                                     int& o00, int& o01, int& o10, int& o11) {
    float py = (float)(h - 1 + ki) + dy;
    float px = (float)(w - 1 + kj) + dx;
    float y0f = floorf(py), x0f = floorf(px);
    float wy = py - y0f, wx = px - x0f;
    int y0 = (int)y0f, x0 = (int)x0f, y1 = y0 + 1, x1 = x0 + 1;
    float my0 = (y0 >= 0 && y0 < HH) ? 1.f : 0.f;
    float my1 = (y1 >= 0 && y1 < HH) ? 1.f : 0.f;
    float mx0 = (x0 >= 0 && x0 < WW) ? 1.f : 0.f;
    float mx1 = (x1 >= 0 && x1 < WW) ? 1.f : 0.f;
    w00 = (1.f - wy) * (1.f - wx) * my0 * mx0;
    w01 = (1.f - wy) * wx         * my0 * mx1;
    w10 = wy         * (1.f - wx) * my1 * mx0;
    w11 = wy         * wx         * my1 * mx1;
    int y0c = min(max(y0, 0), HH - 1), y1c = min(max(y1, 0), HH - 1);
    int x0c = min(max(x0, 0), WW - 1), x1c = min(max(x1, 0), WW - 1);
    o00 = y0c * WW + x0c; o01 = y0c * WW + x1c;
    o10 = y1c * WW + x0c; o11 = y1c * WW + x1c;
}

// ---------------- kernel 2: deformable conv, P=2 in y ----------------------
// block (32,8), grid (5,8,32): thread owns pixels (h0+ty, w) and (h0+ty+8, w).
// Weight LDS.128 broadcasts amortized over 2 pixels -> ~33% fewer L1 ops/px.
__global__ void __launch_bounds__(256) deform_kernel(const float* __restrict__ x) {
    __shared__ float swr[16 * 9 * 32];     // [(c*9+k)*32 + o]
    __shared__ float ssum[32], ssq[32];
    const int tid = threadIdx.y * 32 + threadIdx.x;
    for (int i = tid; i < 1152; i += 256)
        ((float4*)swr)[i] = ((const float4*)g_wrt)[i];
    if (threadIdx.y == 0) { ssum[threadIdx.x] = 0.f; ssq[threadIdx.x] = 0.f; }
    __syncthreads();

    const int d = blockIdx.z, h0 = blockIdx.y * 16;
    const int hA = h0 + threadIdx.y, hB = hA + 8;
    const int w = blockIdx.x * 32 + threadIdx.x;
    const int pixA = d * HWSZ + hA * WW + w;
    const int pixB = pixA + 8 * WW;
    const float* xd = x + d * HWSZ;

    u64t accA[16], accB[16];
#pragma unroll
    for (int j = 0; j < 16; j++) { accA[j] = 0ull; accB[j] = 0ull; }

    for (int k = 0; k < 9; k++) {
        const int ki = k / 3, kj = k % 3;
        float dyA = g_off[(2 * k    ) * DHW + pixA];
        float dxA = g_off[(2 * k + 1) * DHW + pixA];
        float dyB = g_off[(2 * k    ) * DHW + pixB];
        float dxB = g_off[(2 * k + 1) * DHW + pixB];
        float a00, a01, a10, a11; int oa0, oa1, oa2, oa3;
        float b00, b01, b10, b11; int ob0, ob1, ob2, ob3;
        bgeo(hA, w, ki, kj, dyA, dxA, a00, a01, a10, a11, oa0, oa1, oa2, oa3);
        bgeo(hB, w, ki, kj, dyB, dxB, b00, b01, b10, b11, ob0, ob1, ob2, ob3);

#pragma unroll 4
        for (int c = 0; c < 16; c++) {
            const float* xc = xd + c * DHW;
            float vA = a00 * __ldg(xc + oa0) + a01 * __ldg(xc + oa1)
                     + a10 * __ldg(xc + oa2) + a11 * __ldg(xc + oa3);
            float vB = b00 * __ldg(xc + ob0) + b01 * __ldg(xc + ob1)
                     + b10 * __ldg(xc + ob2) + b11 * __ldg(xc + ob3);
            u64t vA2 = pack2(vA, vA);
            u64t vB2 = pack2(vB, vB);
            const ulonglong2* wp = (const ulonglong2*)&swr[(c * 9 + k) * 32];
#pragma unroll
            for (int q = 0; q < 8; q++) {
                ulonglong2 t2 = wp[q];
                fma2(accA[2 * q    ], vA2, t2.x);
                fma2(accA[2 * q + 1], vA2, t2.y);
                fma2(accB[2 * q    ], vB2, t2.x);
                fma2(accB[2 * q + 1], vB2, t2.y);
            }
        }
    }

#pragma unroll
    for (int o = 0; o < 32; o++) {
        float2 pA = unpack2(accA[o >> 1]);
        float2 pB = unpack2(accB[o >> 1]);
        float vA = (o & 1) ? pA.y : pA.x;
        float vB = (o & 1) ? pB.y : pB.x;
        g_t1[o * DHW + pixA] = vA;
        g_t1[o * DHW + pixB] = vB;
        float s = vA + vB, q = vA * vA + vB * vB;
#pragma unroll
        for (int sh = 16; sh > 0; sh >>= 1) {
            s += __shfl_xor_sync(0xffffffffu, s, sh);
            q += __shfl_xor_sync(0xffffffffu, q, sh);
        }
        if (threadIdx.x == 0) { atomicAdd(&ssum[o], s); atomicAdd(&ssq[o], q); }
    }
    __syncthreads();
    if (threadIdx.y == 0) {
        atomicAdd(&g_s1sum[threadIdx.x * DD + d], ssum[threadIdx.x]);
        atomicAdd(&g_s1sq [threadIdx.x * DD + d], ssq [threadIdx.x]);
    }
}

// ---------------- kernel 3: fold BN1 stats into scale/shift ----------------
__global__ void bnstats1_kernel(const float* __restrict__ g1,
                                const float* __restrict__ b1) {
    int i = blockIdx.x * blockDim.x + threadIdx.x;
    if (i < COUT_ * DD) {
        int o = i / DD;
        float n = (float)HWSZ;
        float m = g_s1sum[i] / n;
        float v = g_s1sq[i] / n - m * m;
        float a = g1[o] * rsqrtf(fmaxf(v, 0.f) + 1e-5f);
        g_a1[i] = a;
        g_b1f[i] = b1[o] - m * a;
    }
}

// ---------------- conv3d body, P=2 in y, plane-row staging ------------------
template <int CI, bool FUSE_BN1>
__device__ __forceinline__ void conv3d_body(const float* __restrict__ in,
                                            const float* __restrict__ gwt,
                                            float* __restrict__ out,
                                            float* gsum, float* gsq) {
    __shared__ float tile[12 * 612];          // [p][r][xx], p=cl*3+dz, 18x34
    __shared__ float wsh[4 * 27 * 32];        // [(cl*27+t)*32 + o]
    __shared__ float ssum[32], ssq[32];
    const int tid  = threadIdx.y * 32 + threadIdx.x;
    const int warp = tid >> 5, lane = tid & 31;
    const int d = blockIdx.z, h0 = blockIdx.y * 16, w0 = blockIdx.x * 32;
    if (threadIdx.y == 0) { ssum[threadIdx.x] = 0.f; ssq[threadIdx.x] = 0.f; }

    u64t accA[16], accB[16];
#pragma unroll
    for (int j = 0; j < 16; j++) { accA[j] = 0ull; accB[j] = 0ull; }

    for (int chunk = 0; chunk < CI / 4; chunk++) {
        __syncthreads();
        // weights: coalesced float4 copy from pre-transposed global
        {
            const float4* src = (const float4*)(gwt + chunk * 3456);
            for (int i = tid; i < 864; i += 256) ((float4*)wsh)[i] = src[i];
        }
        // tile: 12 planes x 18 rows x cols[-1..32], warp-per-row, no div/mod
#pragma unroll
        for (int p = 0; p < 12; p++) {
            const int cl = p / 3, dz = p % 3;        // compile-time (p unrolled)
            const int cg = chunk * 4 + cl;
            const int dd = d + dz - 1;
            const bool dok = (dd >= 0) && (dd < DD);
            float aa = 0.f, bb = 0.f;
            if (FUSE_BN1 && dok) { aa = g_a1[cg * DD + dd]; bb = g_b1f[cg * DD + dd]; }
            const float* rowbase = in + (size_t)cg * DHW + dd * HWSZ + w0;
            float* dstp = tile + p * 612;
            for (int r = warp; r < 18; r += 8) {
                int hh = h0 + r - 1;
                bool ok = dok && (hh >= 0) && (hh < HH);
                const float* rp = rowbase + hh * WW;
                float* dst = dstp + r * 34;
                float v = 0.f;
                if (ok) {
                    v = rp[lane];
                    if (FUSE_BN1) v = fmaxf(fmaf(v, aa, bb), 0.f);
                }
                dst[1 + lane] = v;
                if (lane < 2) {
                    int ww_ = lane ? 32 : -1;
                    float e = 0.f;
                    if (ok && (unsigned)(w0 + ww_) < (unsigned)WW) {
                        e = rp[ww_];
                        if (FUSE_BN1) e = fmaxf(fmaf(e, aa, bb), 0.f);
                    }
                    dst[lane ? 33 : 0] = e;
                }
            }
        }
        __syncthreads();

#pragma unroll 1
        for (int cl = 0; cl < 4; cl++) {
#pragma unroll
            for (int t = 0; t < 27; t++) {
                int dz = t / 9, ky = (t / 3) % 3, kx = t % 3;
                int base = cl * 1836 + dz * 612 + threadIdx.x + kx;
                float sA = tile[base + (threadIdx.y + ky) * 34];
                float sB = tile[base + (threadIdx.y + 8 + ky) * 34];
                u64t sA2 = pack2(sA, sA);
                u64t sB2 = pack2(sB, sB);
                const ulonglong2* wp = (const ulonglong2*)&wsh[(cl * 27 + t) * 32];
#pragma unroll
                for (int q = 0; q < 8; q++) {
                    ulonglong2 t2 = wp[q];
                    fma2(accA[2 * q    ], sA2, t2.x);
                    fma2(accA[2 * q + 1], sA2, t2.y);
                    fma2(accB[2 * q    ], sB2, t2.x);
                    fma2(accB[2 * q + 1], sB2, t2.y);
                }
            }
        }
    }

    const int pixA = d * HWSZ + (h0 + threadIdx.y) * WW + (w0 + threadIdx.x);
    const int pixB = pixA + 8 * WW;
#pragma unroll
    for (int o = 0; o < 32; o++) {
        float2 pA = unpack2(accA[o >> 1]);
        float2 pB = unpack2(accB[o >> 1]);
        float vA = (o & 1) ? pA.y : pA.x;
        float vB = (o & 1) ? pB.y : pB.x;
        out[o * DHW + pixA] = vA;
        out[o * DHW + pixB] = vB;
        float s = vA + vB, q = vA * vA + vB * vB;
#pragma unroll
        for (int sh = 16; sh > 0; sh >>= 1) {
            s += __shfl_xor_sync(0xffffffffu, s, sh);
            q += __shfl_xor_sync(0xffffffffu, q, sh);
        }
        if (threadIdx.x == 0) { atomicAdd(&ssum[o], s); atomicAdd(&ssq[o], q); }
    }
    __syncthreads();
    if (threadIdx.y == 0) {
        atomicAdd(&gsum[threadIdx.x], ssum[threadIdx.x]);
        atomicAdd(&gsq [threadIdx.x], ssq [threadIdx.x]);
    }
}

__global__ void __launch_bounds__(256) conv3d_u_kernel() {
    conv3d_body<32, true>(g_t1, g_w2t, g_u, g_s2sum, g_s2sq);
}
__global__ void __launch_bounds__(256) conv3d_id_kernel(const float* __restrict__ x) {
    conv3d_body<16, false>(x, g_wdt, g_id, g_sdsum, g_sdsq);
}

// ---------------- kernel 5: fold BN2 / BNd stats ---------------------------
__global__ void bnstats2_kernel(const float* __restrict__ g2,
                                const float* __restrict__ b2,
                                const float* __restrict__ gd,
                                const float* __restrict__ bd) {
    int i = threadIdx.x;
    float n = (float)DHW;
    if (i < 32) {
        float m = g_s2sum[i] / n;
        float v = g_s2sq[i] / n - m * m;
        float a = g2[i] * rsqrtf(fmaxf(v, 0.f) + 1e-5f);
        g_a2[i] = a; g_b2f[i] = b2[i] - m * a;
    } else if (i < 64) {
        int o = i - 32;
        float m = g_sdsum[o] / n;
        float v = g_sdsq[o] / n - m * m;
        float a = gd[o] * rsqrtf(fmaxf(v, 0.f) + 1e-5f);
        g_ad[o] = a; g_bdf[o] = bd[o] - m * a;
    }
}

// ---------------- kernel 6: out = relu(bn(u) + bn(id)), float4 -------------
__global__ void final_kernel(float* __restrict__ out) {
    int o = blockIdx.z, d = blockIdx.y;
    int base = o * DHW + d * HWSZ + (blockIdx.x * 256 + threadIdx.x) * 4;
    float4 u  = *(const float4*)&g_u[base];
    float4 id = *(const float4*)&g_id[base];
    float a2 = g_a2[o], ad = g_ad[o];
    float bb = g_b2f[o] + g_bdf[o];
    float4 r;
    r.x = fmaxf(fmaf(u.x, a2, fmaf(id.x, ad, bb)), 0.f);
    r.y = fmaxf(fmaf(u.y, a2, fmaf(id.y, ad, bb)), 0.f);
    r.z = fmaxf(fmaf(u.z, a2, fmaf(id.z, ad, bb)), 0.f);
    r.w = fmaxf(fmaf(u.w, a2, fmaf(id.w, ad, bb)), 0.f);
    *(float4*)&out[base] = r;
}

// ---------------------------------------------------------------------------
extern "C" void kernel_launch(void* const* d_in, const int* in_sizes, int n_in,
                              void* d_out, int out_size) {
    const float* x     = (const float*)d_in[0];
    const float* f     = (const float*)d_in[1];
    const float* w_off = (const float*)d_in[2];
    const float* w_reg = (const float*)d_in[3];
    const float* g1    = (const float*)d_in[4];
    const float* b1    = (const float*)d_in[5];
    const float* w2    = (const float*)d_in[6];
    const float* g2    = (const float*)d_in[7];
    const float* b2    = (const float*)d_in[8];
    const float* wd    = (const float*)d_in[9];
    const float* gd    = (const float*)d_in[10];
    const float* bd    = (const float*)d_in[11];
    float* out = (float*)d_out;

    const int smem_off = 12384 * 4;       // 49536 B > 48K static limit
    cudaFuncSetAttribute(offset_kernel,
        cudaFuncAttributeMaxDynamicSharedMemorySize, smem_off);

    dim3 blk(32, 8);
    dim3 grd(WW / 32, HH / 16, DD);       // (5,8,32): all P=2 kernels
    dim3 ew4(HWSZ / 1024, DD, COUT_);     // (20,32,32) final, float4/thread

    zero_stats_kernel<<<9, 256>>>();
    prep_weights_kernel<<<108, 256>>>(w2, wd, w_reg, w_off);
    offset_kernel<<<grd, blk, smem_off>>>(f);
    deform_kernel<<<grd, blk>>>(x);
    bnstats1_kernel<<<4, 256>>>(g1, b1);
    conv3d_u_kernel<<<grd, blk>>>();      // BN1+ReLU fused into tile load
    conv3d_id_kernel<<<grd, blk>>>(x);
    bnstats2_kernel<<<1, 64>>>(g2, b2, gd, bd);
    final_kernel<<<ew4, 256>>>(out);
}

// round 10
// speedup vs baseline: 1.0403x; 1.0403x over previous
#include <cuda_runtime.h>

#define DD   32
#define HH   128
#define WW   160
#define HWSZ (HH*WW)          // 20480
#define DHW  (DD*HWSZ)        // 655360
#define CIN_ 16
#define COUT_ 32

// ---------------- packed f32x2 helpers (Blackwell FFMA2 path) --------------
typedef unsigned long long u64t;

__device__ __forceinline__ u64t pack2(float a, float b) {
    u64t r;
    asm("mov.b64 %0, {%1, %2};" : "=l"(r) : "f"(a), "f"(b));
    return r;
}
__device__ __forceinline__ void fma2(u64t& d, u64t a, u64t b) {
    asm("fma.rn.f32x2 %0, %1, %2, %0;" : "+l"(d) : "l"(a), "l"(b));
}
__device__ __forceinline__ float2 unpack2(u64t v) {
    float2 r;
    asm("mov.b64 {%0, %1}, %2;" : "=f"(r.x), "=f"(r.y) : "l"(v));
    return r;
}

// ---------------- scratch (allocation-free: device globals) ----------------
__device__ float g_off[18 * DHW];        // clipped offsets, [j][d][h][w]
__device__ float g_t1 [COUT_ * DHW];     // deformable conv out (raw, pre-BN1)
__device__ float g_u  [COUT_ * DHW];     // conv3d(w2) out
__device__ float g_id [COUT_ * DHW];     // conv3d(wd) out
__device__ float g_s1sum[COUT_ * DD], g_s1sq[COUT_ * DD];
__device__ float g_s2sum[COUT_], g_s2sq[COUT_], g_sdsum[COUT_], g_sdsq[COUT_];
__device__ float g_a1[COUT_ * DD], g_b1f[COUT_ * DD];
__device__ float g_a2[COUT_], g_b2f[COUT_], g_ad[COUT_], g_bdf[COUT_];
// pre-transposed weights (exact smem layout -> coalesced float4 staging)
__device__ float g_w2t[8 * 3456];        // [chunk][(cl*27+t)*32 + o]
__device__ float g_wdt[4 * 3456];        // [chunk][(cl*27+t)*32 + o]
__device__ float g_wrt[4608];            // [(c*9+k)*32 + o]
__device__ float g_wot[2592];            // [(c*9+k)*18 + j]

// ---------------- kernel 0: zero the stat accumulators ---------------------
__global__ void zero_stats_kernel() {
    int i = blockIdx.x * blockDim.x + threadIdx.x;
    if (i < COUT_ * DD) { g_s1sum[i] = 0.f; g_s1sq[i] = 0.f; }
    if (i < COUT_)      { g_s2sum[i] = 0.f; g_s2sq[i] = 0.f;
                          g_sdsum[i] = 0.f; g_sdsq[i] = 0.f; }
}

// ---------------- kernel 0b: weight pre-transpose --------------------------
__global__ void prep_weights_kernel(const float* __restrict__ w2,
                                    const float* __restrict__ wd,
                                    const float* __restrict__ w_reg,
                                    const float* __restrict__ w_off) {
    int i = blockIdx.x * blockDim.x + threadIdx.x;
    if (i < 27648) {                       // w2
        int o = i & 31, r = i >> 5;
        g_w2t[i] = w2[(o * 32 + r / 27) * 27 + r % 27];
    }
    if (i < 13824) {                       // wd
        int o = i & 31, r = i >> 5;
        g_wdt[i] = wd[(o * 16 + r / 27) * 27 + r % 27];
    }
    if (i < 4608) {
        int o = i & 31, ck = i >> 5;
        g_wrt[i] = w_reg[o * 144 + ck];
    }
    if (i < 2592) {
        int j = i % 18, ck = i / 18;
        g_wot[i] = w_off[j * 144 + ck];
    }
}

// ---------------- kernel 1: offset conv2d (R7 version, P=1) ----------------
__global__ void offset_kernel(const float* __restrict__ f) {
    __shared__ float sw[16 * 9 * 18];      // [(c*9+k)*18 + j]
    __shared__ float sf[16 * 10 * 34];     // [c][yy][xx]
    const int tid = threadIdx.y * 32 + threadIdx.x;
    for (int i = tid; i < 648; i += 256)
        ((float4*)sw)[i] = ((const float4*)g_wot)[i];
    const int d = blockIdx.z, h0 = blockIdx.y * 8, w0 = blockIdx.x * 32;
    for (int i = tid; i < 16 * 340; i += 256) {
        int c = i / 340, r = i % 340, yy = r / 34, xx = r % 34;
        int hh = h0 + yy - 1, ww = w0 + xx - 1;
        float v = 0.f;
        if (hh >= 0 && hh < HH && ww >= 0 && ww < WW)
            v = f[c * DHW + d * HWSZ + hh * WW + ww];
        sf[i] = v;
    }
    __syncthreads();

    u64t off2[9];
#pragma unroll
    for (int j = 0; j < 9; j++) off2[j] = 0ull;
    const int ty = threadIdx.y, tx = threadIdx.x;
    for (int c = 0; c < 16; c++) {
#pragma unroll
        for (int ky = 0; ky < 3; ky++)
#pragma unroll
        for (int kx = 0; kx < 3; kx++) {
            float s = sf[c * 340 + (ty + ky) * 34 + (tx + kx)];
            u64t s2 = pack2(s, s);
            const u64t* wp = (const u64t*)&sw[(c * 9 + ky * 3 + kx) * 18];
#pragma unroll
            for (int j = 0; j < 9; j++) fma2(off2[j], s2, wp[j]);
        }
    }
    const int pix = d * HWSZ + (h0 + ty) * WW + (w0 + tx);
#pragma unroll
    for (int j = 0; j < 9; j++) {
        float2 p = unpack2(off2[j]);
        g_off[(2 * j    ) * DHW + pix] = fminf(1.f, fmaxf(-1.f, p.x));
        g_off[(2 * j + 1) * DHW + pix] = fminf(1.f, fmaxf(-1.f, p.y));
    }
}

// ---------------- kernel 2: deformable conv (R7 version, P=1) --------------
__global__ void deform_kernel(const float* __restrict__ x) {
    __shared__ float swr[16 * 9 * 32];     // [(c*9+k)*32 + o]
    __shared__ float ssum[32], ssq[32];
    const int tid = threadIdx.y * 32 + threadIdx.x;
    for (int i = tid; i < 1152; i += 256)
        ((float4*)swr)[i] = ((const float4*)g_wrt)[i];
    if (threadIdx.y == 0) { ssum[threadIdx.x] = 0.f; ssq[threadIdx.x] = 0.f; }
    __syncthreads();

    const int d = blockIdx.z;
    const int h = blockIdx.y * 8 + threadIdx.y;
    const int w = blockIdx.x * 32 + threadIdx.x;
    const int pix = d * HWSZ + h * WW + w;
    const float* xd = x + d * HWSZ;

    u64t acc2[16];
#pragma unroll
    for (int j = 0; j < 16; j++) acc2[j] = 0ull;

    for (int k = 0; k < 9; k++) {
        float dy = g_off[(2 * k    ) * DHW + pix];
        float dx = g_off[(2 * k + 1) * DHW + pix];
        float py = (float)(h - 1 + k / 3) + dy;
        float px = (float)(w - 1 + k % 3) + dx;
        float y0f = floorf(py), x0f = floorf(px);
        float wy = py - y0f, wx = px - x0f;
        int y0 = (int)y0f, x0 = (int)x0f, y1 = y0 + 1, x1 = x0 + 1;
        float my0 = (y0 >= 0 && y0 < HH) ? 1.f : 0.f;
        float my1 = (y1 >= 0 && y1 < HH) ? 1.f : 0.f;
        float mx0 = (x0 >= 0 && x0 < WW) ? 1.f : 0.f;
        float mx1 = (x1 >= 0 && x1 < WW) ? 1.f : 0.f;
        float w00 = (1.f - wy) * (1.f - wx) * my0 * mx0;
        float w01 = (1.f - wy) * wx         * my0 * mx1;
        float w10 = wy         * (1.f - wx) * my1 * mx0;
        float w11 = wy         * wx         * my1 * mx1;
        int y0c = min(max(y0, 0), HH - 1), y1c = min(max(y1, 0), HH - 1);
        int x0c = min(max(x0, 0), WW - 1), x1c = min(max(x1, 0), WW - 1);
        int o00 = y0c * WW + x0c, o01 = y0c * WW + x1c;
        int o10 = y1c * WW + x0c, o11 = y1c * WW + x1c;

#pragma unroll 4
        for (int c = 0; c < 16; c++) {
            const float* xc = xd + c * DHW;
            float v = w00 * __ldg(xc + o00) + w01 * __ldg(xc + o01)
                    + w10 * __ldg(xc + o10) + w11 * __ldg(xc + o11);
            u64t v2 = pack2(v, v);
            const ulonglong2* wp = (const ulonglong2*)&swr[(c * 9 + k) * 32];
#pragma unroll
            for (int q = 0; q < 8; q++) {
                ulonglong2 t2 = wp[q];
                fma2(acc2[2 * q    ], v2, t2.x);
                fma2(acc2[2 * q + 1], v2, t2.y);
            }
        }
    }

    float av[32];
#pragma unroll
    for (int j = 0; j < 16; j++) {
        float2 p = unpack2(acc2[j]);
        av[2 * j] = p.x; av[2 * j + 1] = p.y;
    }
#pragma unroll
    for (int o = 0; o < 32; o++) g_t1[o * DHW + pix] = av[o];

#pragma unroll
    for (int o = 0; o < 32; o++) {
        float s = av[o], q = av[o] * av[o];
#pragma unroll
        for (int sh = 16; sh > 0; sh >>= 1) {
            s += __shfl_xor_sync(0xffffffffu, s, sh);
            q += __shfl_xor_sync(0xffffffffu, q, sh);
        }
        if (threadIdx.x == 0) { atomicAdd(&ssum[o], s); atomicAdd(&ssq[o], q); }
    }
    __syncthreads();
    if (threadIdx.y == 0) {
        atomicAdd(&g_s1sum[threadIdx.x * DD + d], ssum[threadIdx.x]);
        atomicAdd(&g_s1sq [threadIdx.x * DD + d], ssq [threadIdx.x]);
    }
}

// ---------------- kernel 3: fold BN1 stats into scale/shift ----------------
__global__ void bnstats1_kernel(const float* __restrict__ g1,
                                const float* __restrict__ b1) {
    int i = blockIdx.x * blockDim.x + threadIdx.x;
    if (i < COUT_ * DD) {
        int o = i / DD;
        float n = (float)HWSZ;
        float m = g_s1sum[i] / n;
        float v = g_s1sq[i] / n - m * m;
        float a = g1[o] * rsqrtf(fmaxf(v, 0.f) + 1e-5f);
        g_a1[i] = a;
        g_b1f[i] = b1[o] - m * a;
    }
}

// ---------------- conv3d body, P=2 in y, plane-row staging ------------------
// Mainloop identical to R7 (proven); staging is the R8 plane-row loader:
// fully-unrolled plane loop (cl,dz compile-time), warp-per-row, lane-per-col,
// no div/mod. Cols 1..32 always in-bounds (w0 % 32 == 0); lanes 0/1 do halo.
template <int CI, bool FUSE_BN1>
__device__ __forceinline__ void conv3d_body(const float* __restrict__ in,
                                            const float* __restrict__ gwt,
                                            float* __restrict__ out,
                                            float* gsum, float* gsq) {
    __shared__ float tile[12 * 612];          // [p][r][xx], p=cl*3+dz, 18x34
    __shared__ float wsh[4 * 27 * 32];        // [(cl*27+t)*32 + o]
    __shared__ float ssum[32], ssq[32];
    const int tid  = threadIdx.y * 32 + threadIdx.x;
    const int warp = tid >> 5, lane = tid & 31;
    const int d = blockIdx.z, h0 = blockIdx.y * 16, w0 = blockIdx.x * 32;
    if (threadIdx.y == 0) { ssum[threadIdx.x] = 0.f; ssq[threadIdx.x] = 0.f; }

    u64t accA[16], accB[16];
#pragma unroll
    for (int j = 0; j < 16; j++) { accA[j] = 0ull; accB[j] = 0ull; }

    for (int chunk = 0; chunk < CI / 4; chunk++) {
        __syncthreads();
        // weights: coalesced float4 copy from pre-transposed global
        {
            const float4* src = (const float4*)(gwt + chunk * 3456);
            for (int i = tid; i < 864; i += 256) ((float4*)wsh)[i] = src[i];
        }
        // tile: 12 planes x 18 rows x cols[-1..32], warp-per-row, no div/mod
#pragma unroll
        for (int p = 0; p < 12; p++) {
            const int cl = p / 3, dz = p % 3;        // compile-time (p unrolled)
            const int cg = chunk * 4 + cl;
            const int dd = d + dz - 1;
            const bool dok = (dd >= 0) && (dd < DD);
            float aa = 0.f, bb = 0.f;
            if (FUSE_BN1 && dok) { aa = g_a1[cg * DD + dd]; bb = g_b1f[cg * DD + dd]; }
            const float* rowbase = in + (size_t)cg * DHW + dd * HWSZ + w0;
            float* dstp = tile + p * 612;
            for (int r = warp; r < 18; r += 8) {
                int hh = h0 + r - 1;
                bool ok = dok && (hh >= 0) && (hh < HH);
                const float* rp = rowbase + hh * WW;
                float* dst = dstp + r * 34;
                float v = 0.f;
                if (ok) {
                    v = rp[lane];
                    if (FUSE_BN1) v = fmaxf(fmaf(v, aa, bb), 0.f);
                }
                dst[1 + lane] = v;
                if (lane < 2) {
                    int ww_ = lane ? 32 : -1;
                    float e = 0.f;
                    if (ok && (unsigned)(w0 + ww_) < (unsigned)WW) {
                        e = rp[ww_];
                        if (FUSE_BN1) e = fmaxf(fmaf(e, aa, bb), 0.f);
                    }
                    dst[lane ? 33 : 0] = e;
                }
            }
        }
        __syncthreads();

#pragma unroll 1
        for (int cl = 0; cl < 4; cl++) {
#pragma unroll
            for (int t = 0; t < 27; t++) {
                int dz = t / 9, ky = (t / 3) % 3, kx = t % 3;
                int base = cl * 1836 + dz * 612 + threadIdx.x + kx;
                float sA = tile[base + (threadIdx.y + ky) * 34];
                float sB = tile[base + (threadIdx.y + 8 + ky) * 34];
                u64t sA2 = pack2(sA, sA);
                u64t sB2 = pack2(sB, sB);
                const ulonglong2* wp = (const ulonglong2*)&wsh[(cl * 27 + t) * 32];
#pragma unroll
                for (int q = 0; q < 8; q++) {
                    ulonglong2 t2 = wp[q];
                    fma2(accA[2 * q    ], sA2, t2.x);
                    fma2(accA[2 * q + 1], sA2, t2.y);
                    fma2(accB[2 * q    ], sB2, t2.x);
                    fma2(accB[2 * q + 1], sB2, t2.y);
                }
            }
        }
    }

    const int pixA = d * HWSZ + (h0 + threadIdx.y) * WW + (w0 + threadIdx.x);
    const int pixB = pixA + 8 * WW;
#pragma unroll
    for (int o = 0; o < 32; o++) {
        float2 pA = unpack2(accA[o >> 1]);
        float2 pB = unpack2(accB[o >> 1]);
        float vA = (o & 1) ? pA.y : pA.x;
        float vB = (o & 1) ? pB.y : pB.x;
        out[o * DHW + pixA] = vA;
        out[o * DHW + pixB] = vB;
        float s = vA + vB, q = vA * vA + vB * vB;
#pragma unroll
        for (int sh = 16; sh > 0; sh >>= 1) {
            s += __shfl_xor_sync(0xffffffffu, s, sh);
            q += __shfl_xor_sync(0xffffffffu, q, sh);
        }
        if (threadIdx.x == 0) { atomicAdd(&ssum[o], s); atomicAdd(&ssq[o], q); }
    }
    __syncthreads();
    if (threadIdx.y == 0) {
        atomicAdd(&gsum[threadIdx.x], ssum[threadIdx.x]);
        atomicAdd(&gsq [threadIdx.x], ssq [threadIdx.x]);
    }
}

__global__ void __launch_bounds__(256) conv3d_u_kernel() {
    conv3d_body<32, true>(g_t1, g_w2t, g_u, g_s2sum, g_s2sq);
}
__global__ void __launch_bounds__(256) conv3d_id_kernel(const float* __restrict__ x) {
    conv3d_body<16, false>(x, g_wdt, g_id, g_sdsum, g_sdsq);
}

// ---------------- kernel 5: fold BN2 / BNd stats ---------------------------
__global__ void bnstats2_kernel(const float* __restrict__ g2,
                                const float* __restrict__ b2,
                                const float* __restrict__ gd,
                                const float* __restrict__ bd) {
    int i = threadIdx.x;
    float n = (float)DHW;
    if (i < 32) {
        float m = g_s2sum[i] / n;
        float v = g_s2sq[i] / n - m * m;
        float a = g2[i] * rsqrtf(fmaxf(v, 0.f) + 1e-5f);
        g_a2[i] = a; g_b2f[i] = b2[i] - m * a;
    } else if (i < 64) {
        int o = i - 32;
        float m = g_sdsum[o] / n;
        float v = g_sdsq[o] / n - m * m;
        float a = gd[o] * rsqrtf(fmaxf(v, 0.f) + 1e-5f);
        g_ad[o] = a; g_bdf[o] = bd[o] - m * a;
    }
}

// ---------------- kernel 6: out = relu(bn(u) + bn(id)), float4 -------------
__global__ void final_kernel(float* __restrict__ out) {
    int o = blockIdx.z, d = blockIdx.y;
    int base = o * DHW + d * HWSZ + (blockIdx.x * 256 + threadIdx.x) * 4;
    float4 u  = *(const float4*)&g_u[base];
    float4 id = *(const float4*)&g_id[base];
    float a2 = g_a2[o], ad = g_ad[o];
    float bb = g_b2f[o] + g_bdf[o];
    float4 r;
    r.x = fmaxf(fmaf(u.x, a2, fmaf(id.x, ad, bb)), 0.f);
    r.y = fmaxf(fmaf(u.y, a2, fmaf(id.y, ad, bb)), 0.f);
    r.z = fmaxf(fmaf(u.z, a2, fmaf(id.z, ad, bb)), 0.f);
    r.w = fmaxf(fmaf(u.w, a2, fmaf(id.w, ad, bb)), 0.f);
    *(float4*)&out[base] = r;
}

// ---------------------------------------------------------------------------
extern "C" void kernel_launch(void* const* d_in, const int* in_sizes, int n_in,
                              void* d_out, int out_size) {
    const float* x     = (const float*)d_in[0];
    const float* f     = (const float*)d_in[1];
    const float* w_off = (const float*)d_in[2];
    const float* w_reg = (const float*)d_in[3];
    const float* g1    = (const float*)d_in[4];
    const float* b1    = (const float*)d_in[5];
    const float* w2    = (const float*)d_in[6];
    const float* g2    = (const float*)d_in[7];
    const float* b2    = (const float*)d_in[8];
    const float* wd    = (const float*)d_in[9];
    const float* gd    = (const float*)d_in[10];
    const float* bd    = (const float*)d_in[11];
    float* out = (float*)d_out;

    dim3 blk(32, 8);
    dim3 grd(WW / 32, HH / 8, DD);        // (5,16,32) offset/deform (P=1)
    dim3 grc(WW / 32, HH / 16, DD);       // (5, 8,32) conv3d (P=2 in y)
    dim3 ew4(HWSZ / 1024, DD, COUT_);     // (20,32,32) final, float4/thread

    zero_stats_kernel<<<9, 256>>>();
    prep_weights_kernel<<<108, 256>>>(w2, wd, w_reg, w_off);
    offset_kernel<<<grd, blk>>>(f);
    deform_kernel<<<grd, blk>>>(x);
    bnstats1_kernel<<<4, 256>>>(g1, b1);
    conv3d_u_kernel<<<grc, blk>>>();      // BN1+ReLU fused into tile load
    conv3d_id_kernel<<<grc, blk>>>(x);
    bnstats2_kernel<<<1, 64>>>(g2, b2, gd, bd);
    final_kernel<<<ew4, 256>>>(out);
}

// round 11
// speedup vs baseline: 1.3229x; 1.2716x over previous
#include <cuda_runtime.h>

#define DD   32
#define HH   128
#define WW   160
#define HWSZ (HH*WW)          // 20480
#define DHW  (DD*HWSZ)        // 655360
#define CIN_ 16
#define COUT_ 32

// ---------------- packed f32x2 helpers (Blackwell FFMA2 path) --------------
typedef unsigned long long u64t;

__device__ __forceinline__ u64t pack2(float a, float b) {
    u64t r;
    asm("mov.b64 %0, {%1, %2};" : "=l"(r) : "f"(a), "f"(b));
    return r;
}
__device__ __forceinline__ void fma2(u64t& d, u64t a, u64t b) {
    asm("fma.rn.f32x2 %0, %1, %2, %0;" : "+l"(d) : "l"(a), "l"(b));
}
__device__ __forceinline__ float2 unpack2(u64t v) {
    float2 r;
    asm("mov.b64 {%0, %1}, %2;" : "=f"(r.x), "=f"(r.y) : "l"(v));
    return r;
}

// ---------------- scratch (allocation-free: device globals) ----------------
__device__ float g_off[18 * DHW];        // clipped offsets, [j][d][h][w]
__device__ float g_t1 [COUT_ * DHW];     // deformable conv out (raw, pre-BN1)
__device__ float g_u  [COUT_ * DHW];     // conv3d(w2) out
__device__ float g_id [COUT_ * DHW];     // conv3d(wd) out
__device__ float g_s1sum[COUT_ * DD], g_s1sq[COUT_ * DD];
__device__ float g_s2sum[COUT_], g_s2sq[COUT_], g_sdsum[COUT_], g_sdsq[COUT_];
__device__ float g_a1[COUT_ * DD], g_b1f[COUT_ * DD];
__device__ float g_a2[COUT_], g_b2f[COUT_], g_ad[COUT_], g_bdf[COUT_];
// pre-transposed weights (exact smem layout -> coalesced float4 staging)
__device__ float g_w2t[8 * 3456];        // [chunk][(cl*27+t)*32 + o]
__device__ float g_wdt[4 * 3456];        // [chunk][(cl*27+t)*32 + o]
__device__ float g_wrt[4608];            // [(c*9+k)*32 + o]
__device__ float g_wot[2592];            // [(c*9+k)*18 + j]

// ---------------- kernel 0: zero the stat accumulators ---------------------
__global__ void zero_stats_kernel() {
    int i = blockIdx.x * blockDim.x + threadIdx.x;
    if (i < COUT_ * DD) { g_s1sum[i] = 0.f; g_s1sq[i] = 0.f; }
    if (i < COUT_)      { g_s2sum[i] = 0.f; g_s2sq[i] = 0.f;
                          g_sdsum[i] = 0.f; g_sdsq[i] = 0.f; }
}

// ---------------- kernel 0b: weight pre-transpose --------------------------
__global__ void prep_weights_kernel(const float* __restrict__ w2,
                                    const float* __restrict__ wd,
                                    const float* __restrict__ w_reg,
                                    const float* __restrict__ w_off) {
    int i = blockIdx.x * blockDim.x + threadIdx.x;
    if (i < 27648) {                       // w2
        int o = i & 31, r = i >> 5;
        g_w2t[i] = w2[(o * 32 + r / 27) * 27 + r % 27];
    }
    if (i < 13824) {                       // wd
        int o = i & 31, r = i >> 5;
        g_wdt[i] = wd[(o * 16 + r / 27) * 27 + r % 27];
    }
    if (i < 4608) {
        int o = i & 31, ck = i >> 5;
        g_wrt[i] = w_reg[o * 144 + ck];
    }
    if (i < 2592) {
        int j = i % 18, ck = i / 18;
        g_wot[i] = w_off[j * 144 + ck];
    }
}

// ---------------- kernel 1: offset conv2d (R7 version, P=1) ----------------
__global__ void offset_kernel(const float* __restrict__ f) {
    __shared__ float sw[16 * 9 * 18];      // [(c*9+k)*18 + j]
    __shared__ float sf[16 * 10 * 34];     // [c][yy][xx]
    const int tid = threadIdx.y * 32 + threadIdx.x;
    for (int i = tid; i < 648; i += 256)
        ((float4*)sw)[i] = ((const float4*)g_wot)[i];
    const int d = blockIdx.z, h0 = blockIdx.y * 8, w0 = blockIdx.x * 32;
    for (int i = tid; i < 16 * 340; i += 256) {
        int c = i / 340, r = i % 340, yy = r / 34, xx = r % 34;
        int hh = h0 + yy - 1, ww = w0 + xx - 1;
        float v = 0.f;
        if (hh >= 0 && hh < HH && ww >= 0 && ww < WW)
            v = f[c * DHW + d * HWSZ + hh * WW + ww];
        sf[i] = v;
    }
    __syncthreads();

    u64t off2[9];
#pragma unroll
    for (int j = 0; j < 9; j++) off2[j] = 0ull;
    const int ty = threadIdx.y, tx = threadIdx.x;
    for (int c = 0; c < 16; c++) {
#pragma unroll
        for (int ky = 0; ky < 3; ky++)
#pragma unroll
        for (int kx = 0; kx < 3; kx++) {
            float s = sf[c * 340 + (ty + ky) * 34 + (tx + kx)];
            u64t s2 = pack2(s, s);
            const u64t* wp = (const u64t*)&sw[(c * 9 + ky * 3 + kx) * 18];
#pragma unroll
            for (int j = 0; j < 9; j++) fma2(off2[j], s2, wp[j]);
        }
    }
    const int pix = d * HWSZ + (h0 + ty) * WW + (w0 + tx);
#pragma unroll
    for (int j = 0; j < 9; j++) {
        float2 p = unpack2(off2[j]);
        g_off[(2 * j    ) * DHW + pix] = fminf(1.f, fmaxf(-1.f, p.x));
        g_off[(2 * j + 1) * DHW + pix] = fminf(1.f, fmaxf(-1.f, p.y));
    }
}

// ---------------- kernel 2: deformable conv (R7 version, P=1) --------------
__global__ void deform_kernel(const float* __restrict__ x) {
    __shared__ float swr[16 * 9 * 32];     // [(c*9+k)*32 + o]
    __shared__ float ssum[32], ssq[32];
    const int tid = threadIdx.y * 32 + threadIdx.x;
    for (int i = tid; i < 1152; i += 256)
        ((float4*)swr)[i] = ((const float4*)g_wrt)[i];
    if (threadIdx.y == 0) { ssum[threadIdx.x] = 0.f; ssq[threadIdx.x] = 0.f; }
    __syncthreads();

    const int d = blockIdx.z;
    const int h = blockIdx.y * 8 + threadIdx.y;
    const int w = blockIdx.x * 32 + threadIdx.x;
    const int pix = d * HWSZ + h * WW + w;
    const float* xd = x + d * HWSZ;

    u64t acc2[16];
#pragma unroll
    for (int j = 0; j < 16; j++) acc2[j] = 0ull;

    for (int k = 0; k < 9; k++) {
        float dy = g_off[(2 * k    ) * DHW + pix];
        float dx = g_off[(2 * k + 1) * DHW + pix];
        float py = (float)(h - 1 + k / 3) + dy;
        float px = (float)(w - 1 + k % 3) + dx;
        float y0f = floorf(py), x0f = floorf(px);
        float wy = py - y0f, wx = px - x0f;
        int y0 = (int)y0f, x0 = (int)x0f, y1 = y0 + 1, x1 = x0 + 1;
        float my0 = (y0 >= 0 && y0 < HH) ? 1.f : 0.f;
        float my1 = (y1 >= 0 && y1 < HH) ? 1.f : 0.f;
        float mx0 = (x0 >= 0 && x0 < WW) ? 1.f : 0.f;
        float mx1 = (x1 >= 0 && x1 < WW) ? 1.f : 0.f;
        float w00 = (1.f - wy) * (1.f - wx) * my0 * mx0;
        float w01 = (1.f - wy) * wx         * my0 * mx1;
        float w10 = wy         * (1.f - wx) * my1 * mx0;
        float w11 = wy         * wx         * my1 * mx1;
        int y0c = min(max(y0, 0), HH - 1), y1c = min(max(y1, 0), HH - 1);
        int x0c = min(max(x0, 0), WW - 1), x1c = min(max(x1, 0), WW - 1);
        int o00 = y0c * WW + x0c, o01 = y0c * WW + x1c;
        int o10 = y1c * WW + x0c, o11 = y1c * WW + x1c;

#pragma unroll 4
        for (int c = 0; c < 16; c++) {
            const float* xc = xd + c * DHW;
            float v = w00 * __ldg(xc + o00) + w01 * __ldg(xc + o01)
                    + w10 * __ldg(xc + o10) + w11 * __ldg(xc + o11);
            u64t v2 = pack2(v, v);
            const ulonglong2* wp = (const ulonglong2*)&swr[(c * 9 + k) * 32];
#pragma unroll
            for (int q = 0; q < 8; q++) {
                ulonglong2 t2 = wp[q];
                fma2(acc2[2 * q    ], v2, t2.x);
                fma2(acc2[2 * q + 1], v2, t2.y);
            }
        }
    }

    float av[32];
#pragma unroll
    for (int j = 0; j < 16; j++) {
        float2 p = unpack2(acc2[j]);
        av[2 * j] = p.x; av[2 * j + 1] = p.y;
    }
#pragma unroll
    for (int o = 0; o < 32; o++) g_t1[o * DHW + pix] = av[o];

#pragma unroll
    for (int o = 0; o < 32; o++) {
        float s = av[o], q = av[o] * av[o];
#pragma unroll
        for (int sh = 16; sh > 0; sh >>= 1) {
            s += __shfl_xor_sync(0xffffffffu, s, sh);
            q += __shfl_xor_sync(0xffffffffu, q, sh);
        }
        if (threadIdx.x == 0) { atomicAdd(&ssum[o], s); atomicAdd(&ssq[o], q); }
    }
    __syncthreads();
    if (threadIdx.y == 0) {
        atomicAdd(&g_s1sum[threadIdx.x * DD + d], ssum[threadIdx.x]);
        atomicAdd(&g_s1sq [threadIdx.x * DD + d], ssq [threadIdx.x]);
    }
}

// ---------------- kernel 3: fold BN1 stats into scale/shift ----------------
__global__ void bnstats1_kernel(const float* __restrict__ g1,
                                const float* __restrict__ b1) {
    int i = blockIdx.x * blockDim.x + threadIdx.x;
    if (i < COUT_ * DD) {
        int o = i / DD;
        float n = (float)HWSZ;
        float m = g_s1sum[i] / n;
        float v = g_s1sq[i] / n - m * m;
        float a = g1[o] * rsqrtf(fmaxf(v, 0.f) + 1e-5f);
        g_a1[i] = a;
        g_b1f[i] = b1[o] - m * a;
    }
}

// ---------------- conv3d body, P=2 pixel tiling in y (R7 version) ----------
// Block (32,8) computes a 32x16 output tile: thread owns rows ty and ty+8.
// Every weight LDS.128 feeds 2 pixels worth of FFMA2. Register-minimal
// flat staging loop (div/mod by constants) — proven not to spill.
template <int CI, bool FUSE_BN1>
__device__ __forceinline__ void conv3d_body(const float* __restrict__ in,
                                            const float* __restrict__ gwt,
                                            float* __restrict__ out,
                                            float* gsum, float* gsq) {
    __shared__ float tile[4 * 3 * 18 * 34];   // [cl][dz][yy][xx], yy: h0-1..h0+16
    __shared__ float wsh[4 * 27 * 32];        // [(cl*27+t)*32 + o]
    __shared__ float ssum[32], ssq[32];
    const int tid = threadIdx.y * 32 + threadIdx.x;
    const int d = blockIdx.z, h0 = blockIdx.y * 16, w0 = blockIdx.x * 32;
    if (threadIdx.y == 0) { ssum[threadIdx.x] = 0.f; ssq[threadIdx.x] = 0.f; }

    u64t accA[16], accB[16];
#pragma unroll
    for (int j = 0; j < 16; j++) { accA[j] = 0ull; accB[j] = 0ull; }

    for (int chunk = 0; chunk < CI / 4; chunk++) {
        __syncthreads();
        // stage 4 channels x 3 depth x 18 rows x 34 cols = 7344 floats
        for (int i = tid; i < 7344; i += 256) {
            int cl = i / 1836, r = i % 1836, dz = r / 612;
            int r2 = r % 612, yy = r2 / 34, xx = r2 % 34;
            int dd = d + dz - 1, hh = h0 + yy - 1, ww = w0 + xx - 1;
            float v = 0.f;
            if (dd >= 0 && dd < DD && hh >= 0 && hh < HH && ww >= 0 && ww < WW) {
                int cg = chunk * 4 + cl;
                v = in[cg * DHW + dd * HWSZ + hh * WW + ww];
                if (FUSE_BN1)
                    v = fmaxf(fmaf(v, g_a1[cg * DD + dd], g_b1f[cg * DD + dd]), 0.f);
            }
            tile[i] = v;
        }
        // weights: coalesced float4 copy from pre-transposed global
        {
            const float4* src = (const float4*)(gwt + chunk * 3456);
            for (int i = tid; i < 864; i += 256) ((float4*)wsh)[i] = src[i];
        }
        __syncthreads();

#pragma unroll 1
        for (int cl = 0; cl < 4; cl++) {
#pragma unroll
            for (int t = 0; t < 27; t++) {
                int dz = t / 9, ky = (t / 3) % 3, kx = t % 3;
                int base = cl * 1836 + dz * 612 + threadIdx.x + kx;
                float sA = tile[base + (threadIdx.y + ky) * 34];
                float sB = tile[base + (threadIdx.y + 8 + ky) * 34];
                u64t sA2 = pack2(sA, sA);
                u64t sB2 = pack2(sB, sB);
                const ulonglong2* wp = (const ulonglong2*)&wsh[(cl * 27 + t) * 32];
#pragma unroll
                for (int q = 0; q < 8; q++) {
                    ulonglong2 t2 = wp[q];
                    fma2(accA[2 * q    ], sA2, t2.x);
                    fma2(accA[2 * q + 1], sA2, t2.y);
                    fma2(accB[2 * q    ], sB2, t2.x);
                    fma2(accB[2 * q + 1], sB2, t2.y);
                }
            }
        }
    }

    const int pixA = d * HWSZ + (h0 + threadIdx.y) * WW + (w0 + threadIdx.x);
    const int pixB = pixA + 8 * WW;
#pragma unroll
    for (int o = 0; o < 32; o++) {
        float2 pA = unpack2(accA[o >> 1]);
        float2 pB = unpack2(accB[o >> 1]);
        float vA = (o & 1) ? pA.y : pA.x;
        float vB = (o & 1) ? pB.y : pB.x;
        out[o * DHW + pixA] = vA;
        out[o * DHW + pixB] = vB;
        float s = vA + vB, q = vA * vA + vB * vB;
#pragma unroll
        for (int sh = 16; sh > 0; sh >>= 1) {
            s += __shfl_xor_sync(0xffffffffu, s, sh);
            q += __shfl_xor_sync(0xffffffffu, q, sh);
        }
        if (threadIdx.x == 0) { atomicAdd(&ssum[o], s); atomicAdd(&ssq[o], q); }
    }
    __syncthreads();
    if (threadIdx.y == 0) {
        atomicAdd(&gsum[threadIdx.x], ssum[threadIdx.x]);
        atomicAdd(&gsq [threadIdx.x], ssq [threadIdx.x]);
    }
}

__global__ void __launch_bounds__(256) conv3d_u_kernel() {
    conv3d_body<32, true>(g_t1, g_w2t, g_u, g_s2sum, g_s2sq);
}
__global__ void __launch_bounds__(256) conv3d_id_kernel(const float* __restrict__ x) {
    conv3d_body<16, false>(x, g_wdt, g_id, g_sdsum, g_sdsq);
}

// ---------------- kernel 5: fold BN2 / BNd stats ---------------------------
__global__ void bnstats2_kernel(const float* __restrict__ g2,
                                const float* __restrict__ b2,
                                const float* __restrict__ gd,
                                const float* __restrict__ bd) {
    int i = threadIdx.x;
    float n = (float)DHW;
    if (i < 32) {
        float m = g_s2sum[i] / n;
        float v = g_s2sq[i] / n - m * m;
        float a = g2[i] * rsqrtf(fmaxf(v, 0.f) + 1e-5f);
        g_a2[i] = a; g_b2f[i] = b2[i] - m * a;
    } else if (i < 64) {
        int o = i - 32;
        float m = g_sdsum[o] / n;
        float v = g_sdsq[o] / n - m * m;
        float a = gd[o] * rsqrtf(fmaxf(v, 0.f) + 1e-5f);
        g_ad[o] = a; g_bdf[o] = bd[o] - m * a;
    }
}

// ---------------- kernel 6: out = relu(bn(u) + bn(id)), float4 -------------
__global__ void final_kernel(float* __restrict__ out) {
    int o = blockIdx.z, d = blockIdx.y;
    int base = o * DHW + d * HWSZ + (blockIdx.x * 256 + threadIdx.x) * 4;
    float4 u  = *(const float4*)&g_u[base];
    float4 id = *(const float4*)&g_id[base];
    float a2 = g_a2[o], ad = g_ad[o];
    float bb = g_b2f[o] + g_bdf[o];
    float4 r;
    r.x = fmaxf(fmaf(u.x, a2, fmaf(id.x, ad, bb)), 0.f);
    r.y = fmaxf(fmaf(u.y, a2, fmaf(id.y, ad, bb)), 0.f);
    r.z = fmaxf(fmaf(u.z, a2, fmaf(id.z, ad, bb)), 0.f);
    r.w = fmaxf(fmaf(u.w, a2, fmaf(id.w, ad, bb)), 0.f);
    *(float4*)&out[base] = r;
}

// ---------------- side stream for conv_id overlap ---------------------------
// Created once at static-init time (before harness checkpoints / capture).
// kernel_launch enqueues identical work every call; events fork/join the
// side stream into the capture per the standard CUDA graph-capture pattern.
namespace {
struct SideStream {
    cudaStream_t s2;
    cudaEvent_t ev_fork, ev_join;
    SideStream() {
        cudaStreamCreateWithFlags(&s2, cudaStreamNonBlocking);
        cudaEventCreateWithFlags(&ev_fork, cudaEventDisableTiming);
        cudaEventCreateWithFlags(&ev_join, cudaEventDisableTiming);
    }
};
SideStream g_ss;
}

// ---------------------------------------------------------------------------
extern "C" void kernel_launch(void* const* d_in, const int* in_sizes, int n_in,
                              void* d_out, int out_size) {
    const float* x     = (const float*)d_in[0];
    const float* f     = (const float*)d_in[1];
    const float* w_off = (const float*)d_in[2];
    const float* w_reg = (const float*)d_in[3];
    const float* g1    = (const float*)d_in[4];
    const float* b1    = (const float*)d_in[5];
    const float* w2    = (const float*)d_in[6];
    const float* g2    = (const float*)d_in[7];
    const float* b2    = (const float*)d_in[8];
    const float* wd    = (const float*)d_in[9];
    const float* gd    = (const float*)d_in[10];
    const float* bd    = (const float*)d_in[11];
    float* out = (float*)d_out;

    dim3 blk(32, 8);
    dim3 grd(WW / 32, HH / 8, DD);        // (5,16,32) offset/deform (P=1)
    dim3 grc(WW / 32, HH / 16, DD);       // (5, 8,32) conv3d (P=2 in y)
    dim3 ew4(HWSZ / 1024, DD, COUT_);     // (20,32,32) final, float4/thread

    // main stream: prerequisites for everything
    zero_stats_kernel<<<9, 256>>>();
    prep_weights_kernel<<<108, 256>>>(w2, wd, w_reg, w_off);

    // fork: conv_id depends only on x + prep/zero -> run on side stream,
    // overlapping the offset/deform/bnstats1/conv_u chain.
    cudaEventRecord(g_ss.ev_fork, 0);
    cudaStreamWaitEvent(g_ss.s2, g_ss.ev_fork, 0);
    conv3d_id_kernel<<<grc, blk, 0, g_ss.s2>>>(x);
    cudaEventRecord(g_ss.ev_join, g_ss.s2);

    // main stream: dependent chain
    offset_kernel<<<grd, blk>>>(f);
    deform_kernel<<<grd, blk>>>(x);
    bnstats1_kernel<<<4, 256>>>(g1, b1);
    conv3d_u_kernel<<<grc, blk>>>();      // BN1+ReLU fused into tile load

    // join: bnstats2/final need both conv outputs
    cudaStreamWaitEvent(0, g_ss.ev_join, 0);
    bnstats2_kernel<<<1, 64>>>(g2, b2, gd, bd);
    final_kernel<<<ew4, 256>>>(out);
}

// round 12
// speedup vs baseline: 1.3273x; 1.0033x over previous
#include <cuda_runtime.h>

#define DD   32
#define HH   128
#define WW   160
#define HWSZ (HH*WW)          // 20480
#define DHW  (DD*HWSZ)        // 655360
#define CIN_ 16
#define COUT_ 32

// ---------------- packed f32x2 helpers (Blackwell FFMA2 path) --------------
typedef unsigned long long u64t;

__device__ __forceinline__ u64t pack2(float a, float b) {
    u64t r;
    asm("mov.b64 %0, {%1, %2};" : "=l"(r) : "f"(a), "f"(b));
    return r;
}
__device__ __forceinline__ void fma2(u64t& d, u64t a, u64t b) {
    asm("fma.rn.f32x2 %0, %1, %2, %0;" : "+l"(d) : "l"(a), "l"(b));
}
__device__ __forceinline__ float2 unpack2(u64t v) {
    float2 r;
    asm("mov.b64 {%0, %1}, %2;" : "=f"(r.x), "=f"(r.y) : "l"(v));
    return r;
}

// ---------------- scratch (allocation-free: device globals) ----------------
__device__ float g_off[18 * DHW];        // clipped offsets, [j][d][h][w]
__device__ float g_t1 [COUT_ * DHW];     // deformable conv out (raw, pre-BN1)
__device__ float g_u  [COUT_ * DHW];     // conv3d(w2) out
__device__ float g_id [COUT_ * DHW];     // conv3d(wd) out
__device__ float g_s1sum[COUT_ * DD], g_s1sq[COUT_ * DD];
__device__ float g_s2sum[COUT_], g_s2sq[COUT_], g_sdsum[COUT_], g_sdsq[COUT_];
__device__ float g_a1[COUT_ * DD], g_b1f[COUT_ * DD];
__device__ float g_a2[COUT_], g_b2f[COUT_], g_ad[COUT_], g_bdf[COUT_];
// pre-transposed weights (exact smem layout -> coalesced float4 staging)
__device__ float g_w2t[8 * 3456];        // [chunk][(cl*27+t)*32 + o]
__device__ float g_wdt[4 * 3456];        // [chunk][(cl*27+t)*32 + o]
__device__ float g_wrt[4608];            // [(c*9+k)*32 + o]
__device__ float g_wot[2592];            // [(c*9+k)*18 + j]

// ---------------- kernel 0: zero the stat accumulators ---------------------
__global__ void zero_stats_kernel() {
    int i = blockIdx.x * blockDim.x + threadIdx.x;
    if (i < COUT_ * DD) { g_s1sum[i] = 0.f; g_s1sq[i] = 0.f; }
    if (i < COUT_)      { g_s2sum[i] = 0.f; g_s2sq[i] = 0.f;
                          g_sdsum[i] = 0.f; g_sdsq[i] = 0.f; }
}

// ---------------- kernel 0b: weight pre-transpose --------------------------
__global__ void prep_weights_kernel(const float* __restrict__ w2,
                                    const float* __restrict__ wd,
                                    const float* __restrict__ w_reg,
                                    const float* __restrict__ w_off) {
    int i = blockIdx.x * blockDim.x + threadIdx.x;
    if (i < 27648) {                       // w2
        int o = i & 31, r = i >> 5;
        g_w2t[i] = w2[(o * 32 + r / 27) * 27 + r % 27];
    }
    if (i < 13824) {                       // wd
        int o = i & 31, r = i >> 5;
        g_wdt[i] = wd[(o * 16 + r / 27) * 27 + r % 27];
    }
    if (i < 4608) {
        int o = i & 31, ck = i >> 5;
        g_wrt[i] = w_reg[o * 144 + ck];
    }
    if (i < 2592) {
        int j = i % 18, ck = i / 18;
        g_wot[i] = w_off[j * 144 + ck];
    }
}

// ---------------- kernel 1: offset conv2d (R7 version, P=1) ----------------
__global__ void offset_kernel(const float* __restrict__ f) {
    __shared__ float sw[16 * 9 * 18];      // [(c*9+k)*18 + j]
    __shared__ float sf[16 * 10 * 34];     // [c][yy][xx]
    const int tid = threadIdx.y * 32 + threadIdx.x;
    for (int i = tid; i < 648; i += 256)
        ((float4*)sw)[i] = ((const float4*)g_wot)[i];
    const int d = blockIdx.z, h0 = blockIdx.y * 8, w0 = blockIdx.x * 32;
    for (int i = tid; i < 16 * 340; i += 256) {
        int c = i / 340, r = i % 340, yy = r / 34, xx = r % 34;
        int hh = h0 + yy - 1, ww = w0 + xx - 1;
        float v = 0.f;
        if (hh >= 0 && hh < HH && ww >= 0 && ww < WW)
            v = f[c * DHW + d * HWSZ + hh * WW + ww];
        sf[i] = v;
    }
    __syncthreads();

    u64t off2[9];
#pragma unroll
    for (int j = 0; j < 9; j++) off2[j] = 0ull;
    const int ty = threadIdx.y, tx = threadIdx.x;
    for (int c = 0; c < 16; c++) {
#pragma unroll
        for (int ky = 0; ky < 3; ky++)
#pragma unroll
        for (int kx = 0; kx < 3; kx++) {
            float s = sf[c * 340 + (ty + ky) * 34 + (tx + kx)];
            u64t s2 = pack2(s, s);
            const u64t* wp = (const u64t*)&sw[(c * 9 + ky * 3 + kx) * 18];
#pragma unroll
            for (int j = 0; j < 9; j++) fma2(off2[j], s2, wp[j]);
        }
    }
    const int pix = d * HWSZ + (h0 + ty) * WW + (w0 + tx);
#pragma unroll
    for (int j = 0; j < 9; j++) {
        float2 p = unpack2(off2[j]);
        g_off[(2 * j    ) * DHW + pix] = fminf(1.f, fmaxf(-1.f, p.x));
        g_off[(2 * j + 1) * DHW + pix] = fminf(1.f, fmaxf(-1.f, p.y));
    }
}

// ---------------- kernel 2: deformable conv, smem-staged gathers -----------
// Offsets are clipped to [-1,1], so every bilinear sample for an 8x32 tile
// lies in rows [h0-2, h0+10], cols [w0-2, w0+35]: stage that 13x38 window
// per channel in smem and gather via LDS (1 wavefront) instead of scattered
// LDG (~2+ wavefronts). Border clamps provably stay inside the window.
#define TROWS 13
#define TCOLS 38
#define TSZ   (TROWS * TCOLS)   // 494
__global__ void __launch_bounds__(256) deform_kernel(const float* __restrict__ x) {
    extern __shared__ float sm[];
    float* swr  = sm;                    // 4608: [(c*9+k)*32 + o]
    float* sx   = sm + 4608;             // 16*494 = 7904: [c][ty][tx]
    float* ssum = sm + 12512;            // 32
    float* ssq  = sm + 12544;            // 32  (total 12576 floats = 50304 B)

    const int tid = threadIdx.y * 32 + threadIdx.x;
    for (int i = tid; i < 1152; i += 256)
        ((float4*)swr)[i] = ((const float4*)g_wrt)[i];
    if (threadIdx.y == 0) { ssum[threadIdx.x] = 0.f; ssq[threadIdx.x] = 0.f; }

    const int d = blockIdx.z, h0 = blockIdx.y * 8, w0 = blockIdx.x * 32;
    const float* xd = x + d * HWSZ;

    // stage x window: 16 ch x 13 rows x 38 cols, zero-padded at borders
    for (int i = tid; i < 16 * TSZ; i += 256) {
        int c = i / TSZ, r = i % TSZ, yy = r / TCOLS, xx = r % TCOLS;
        int hh = h0 + yy - 2, ww = w0 + xx - 2;
        float v = 0.f;
        if (hh >= 0 && hh < HH && ww >= 0 && ww < WW)
            v = xd[c * DHW + hh * WW + ww];
        sx[i] = v;
    }
    __syncthreads();

    const int h = h0 + threadIdx.y;
    const int w = w0 + threadIdx.x;
    const int pix = d * HWSZ + h * WW + w;

    u64t acc2[16];
#pragma unroll
    for (int j = 0; j < 16; j++) acc2[j] = 0ull;

    for (int k = 0; k < 9; k++) {
        float dy = g_off[(2 * k    ) * DHW + pix];
        float dx = g_off[(2 * k + 1) * DHW + pix];
        float py = (float)(h - 1 + k / 3) + dy;
        float px = (float)(w - 1 + k % 3) + dx;
        float y0f = floorf(py), x0f = floorf(px);
        float wy = py - y0f, wx = px - x0f;
        int y0 = (int)y0f, x0 = (int)x0f, y1 = y0 + 1, x1 = x0 + 1;
        float my0 = (y0 >= 0 && y0 < HH) ? 1.f : 0.f;
        float my1 = (y1 >= 0 && y1 < HH) ? 1.f : 0.f;
        float mx0 = (x0 >= 0 && x0 < WW) ? 1.f : 0.f;
        float mx1 = (x1 >= 0 && x1 < WW) ? 1.f : 0.f;
        float w00 = (1.f - wy) * (1.f - wx) * my0 * mx0;
        float w01 = (1.f - wy) * wx         * my0 * mx1;
        float w10 = wy         * (1.f - wx) * my1 * mx0;
        float w11 = wy         * wx         * my1 * mx1;
        // tile-local clamped coords (always inside the staged window)
        int ty0 = min(max(y0, 0), HH - 1) - h0 + 2;
        int ty1 = min(max(y1, 0), HH - 1) - h0 + 2;
        int tx0 = min(max(x0, 0), WW - 1) - w0 + 2;
        int tx1 = min(max(x1, 0), WW - 1) - w0 + 2;
        int o00 = ty0 * TCOLS + tx0, o01 = ty0 * TCOLS + tx1;
        int o10 = ty1 * TCOLS + tx0, o11 = ty1 * TCOLS + tx1;

#pragma unroll 4
        for (int c = 0; c < 16; c++) {
            const float* xc = sx + c * TSZ;
            float v = w00 * xc[o00] + w01 * xc[o01]
                    + w10 * xc[o10] + w11 * xc[o11];
            u64t v2 = pack2(v, v);
            const ulonglong2* wp = (const ulonglong2*)&swr[(c * 9 + k) * 32];
#pragma unroll
            for (int q = 0; q < 8; q++) {
                ulonglong2 t2 = wp[q];
                fma2(acc2[2 * q    ], v2, t2.x);
                fma2(acc2[2 * q + 1], v2, t2.y);
            }
        }
    }

    float av[32];
#pragma unroll
    for (int j = 0; j < 16; j++) {
        float2 p = unpack2(acc2[j]);
        av[2 * j] = p.x; av[2 * j + 1] = p.y;
    }
#pragma unroll
    for (int o = 0; o < 32; o++) g_t1[o * DHW + pix] = av[o];

#pragma unroll
    for (int o = 0; o < 32; o++) {
        float s = av[o], q = av[o] * av[o];
#pragma unroll
        for (int sh = 16; sh > 0; sh >>= 1) {
            s += __shfl_xor_sync(0xffffffffu, s, sh);
            q += __shfl_xor_sync(0xffffffffu, q, sh);
        }
        if (threadIdx.x == 0) { atomicAdd(&ssum[o], s); atomicAdd(&ssq[o], q); }
    }
    __syncthreads();
    if (threadIdx.y == 0) {
        atomicAdd(&g_s1sum[threadIdx.x * DD + d], ssum[threadIdx.x]);
        atomicAdd(&g_s1sq [threadIdx.x * DD + d], ssq [threadIdx.x]);
    }
}

// ---------------- kernel 3: fold BN1 stats into scale/shift ----------------
__global__ void bnstats1_kernel(const float* __restrict__ g1,
                                const float* __restrict__ b1) {
    int i = blockIdx.x * blockDim.x + threadIdx.x;
    if (i < COUT_ * DD) {
        int o = i / DD;
        float n = (float)HWSZ;
        float m = g_s1sum[i] / n;
        float v = g_s1sq[i] / n - m * m;
        float a = g1[o] * rsqrtf(fmaxf(v, 0.f) + 1e-5f);
        g_a1[i] = a;
        g_b1f[i] = b1[o] - m * a;
    }
}

// ---------------- conv3d body, P=2 pixel tiling in y (R7 version) ----------
template <int CI, bool FUSE_BN1>
__device__ __forceinline__ void conv3d_body(const float* __restrict__ in,
                                            const float* __restrict__ gwt,
                                            float* __restrict__ out,
                                            float* gsum, float* gsq) {
    __shared__ float tile[4 * 3 * 18 * 34];   // [cl][dz][yy][xx], yy: h0-1..h0+16
    __shared__ float wsh[4 * 27 * 32];        // [(cl*27+t)*32 + o]
    __shared__ float ssum[32], ssq[32];
    const int tid = threadIdx.y * 32 + threadIdx.x;
    const int d = blockIdx.z, h0 = blockIdx.y * 16, w0 = blockIdx.x * 32;
    if (threadIdx.y == 0) { ssum[threadIdx.x] = 0.f; ssq[threadIdx.x] = 0.f; }

    u64t accA[16], accB[16];
#pragma unroll
    for (int j = 0; j < 16; j++) { accA[j] = 0ull; accB[j] = 0ull; }

    for (int chunk = 0; chunk < CI / 4; chunk++) {
        __syncthreads();
        // stage 4 channels x 3 depth x 18 rows x 34 cols = 7344 floats
        for (int i = tid; i < 7344; i += 256) {
            int cl = i / 1836, r = i % 1836, dz = r / 612;
            int r2 = r % 612, yy = r2 / 34, xx = r2 % 34;
            int dd = d + dz - 1, hh = h0 + yy - 1, ww = w0 + xx - 1;
            float v = 0.f;
            if (dd >= 0 && dd < DD && hh >= 0 && hh < HH && ww >= 0 && ww < WW) {
                int cg = chunk * 4 + cl;
                v = in[cg * DHW + dd * HWSZ + hh * WW + ww];
                if (FUSE_BN1)
                    v = fmaxf(fmaf(v, g_a1[cg * DD + dd], g_b1f[cg * DD + dd]), 0.f);
            }
            tile[i] = v;
        }
        // weights: coalesced float4 copy from pre-transposed global
        {
            const float4* src = (const float4*)(gwt + chunk * 3456);
            for (int i = tid; i < 864; i += 256) ((float4*)wsh)[i] = src[i];
        }
        __syncthreads();

#pragma unroll 1
        for (int cl = 0; cl < 4; cl++) {
#pragma unroll
            for (int t = 0; t < 27; t++) {
                int dz = t / 9, ky = (t / 3) % 3, kx = t % 3;
                int base = cl * 1836 + dz * 612 + threadIdx.x + kx;
                float sA = tile[base + (threadIdx.y + ky) * 34];
                float sB = tile[base + (threadIdx.y + 8 + ky) * 34];
                u64t sA2 = pack2(sA, sA);
                u64t sB2 = pack2(sB, sB);
                const ulonglong2* wp = (const ulonglong2*)&wsh[(cl * 27 + t) * 32];
#pragma unroll
                for (int q = 0; q < 8; q++) {
                    ulonglong2 t2 = wp[q];
                    fma2(accA[2 * q    ], sA2, t2.x);
                    fma2(accA[2 * q + 1], sA2, t2.y);
                    fma2(accB[2 * q    ], sB2, t2.x);
                    fma2(accB[2 * q + 1], sB2, t2.y);
                }
            }
        }
    }

    const int pixA = d * HWSZ + (h0 + threadIdx.y) * WW + (w0 + threadIdx.x);
    const int pixB = pixA + 8 * WW;
#pragma unroll
    for (int o = 0; o < 32; o++) {
        float2 pA = unpack2(accA[o >> 1]);
        float2 pB = unpack2(accB[o >> 1]);
        float vA = (o & 1) ? pA.y : pA.x;
        float vB = (o & 1) ? pB.y : pB.x;
        out[o * DHW + pixA] = vA;
        out[o * DHW + pixB] = vB;
        float s = vA + vB, q = vA * vA + vB * vB;
#pragma unroll
        for (int sh = 16; sh > 0; sh >>= 1) {
            s += __shfl_xor_sync(0xffffffffu, s, sh);
            q += __shfl_xor_sync(0xffffffffu, q, sh);
        }
        if (threadIdx.x == 0) { atomicAdd(&ssum[o], s); atomicAdd(&ssq[o], q); }
    }
    __syncthreads();
    if (threadIdx.y == 0) {
        atomicAdd(&gsum[threadIdx.x], ssum[threadIdx.x]);
        atomicAdd(&gsq [threadIdx.x], ssq [threadIdx.x]);
    }
}

__global__ void __launch_bounds__(256) conv3d_u_kernel() {
    conv3d_body<32, true>(g_t1, g_w2t, g_u, g_s2sum, g_s2sq);
}
__global__ void __launch_bounds__(256) conv3d_id_kernel(const float* __restrict__ x) {
    conv3d_body<16, false>(x, g_wdt, g_id, g_sdsum, g_sdsq);
}

// ---------------- kernel 5: fold BN2 / BNd stats ---------------------------
__global__ void bnstats2_kernel(const float* __restrict__ g2,
                                const float* __restrict__ b2,
                                const float* __restrict__ gd,
                                const float* __restrict__ bd) {
    int i = threadIdx.x;
    float n = (float)DHW;
    if (i < 32) {
        float m = g_s2sum[i] / n;
        float v = g_s2sq[i] / n - m * m;
        float a = g2[i] * rsqrtf(fmaxf(v, 0.f) + 1e-5f);
        g_a2[i] = a; g_b2f[i] = b2[i] - m * a;
    } else if (i < 64) {
        int o = i - 32;
        float m = g_sdsum[o] / n;
        float v = g_sdsq[o] / n - m * m;
        float a = gd[o] * rsqrtf(fmaxf(v, 0.f) + 1e-5f);
        g_ad[o] = a; g_bdf[o] = bd[o] - m * a;
    }
}

// ---------------- kernel 6: out = relu(bn(u) + bn(id)), float4 -------------
__global__ void final_kernel(float* __restrict__ out) {
    int o = blockIdx.z, d = blockIdx.y;
    int base = o * DHW + d * HWSZ + (blockIdx.x * 256 + threadIdx.x) * 4;
    float4 u  = *(const float4*)&g_u[base];
    float4 id = *(const float4*)&g_id[base];
    float a2 = g_a2[o], ad = g_ad[o];
    float bb = g_b2f[o] + g_bdf[o];
    float4 r;
    r.x = fmaxf(fmaf(u.x, a2, fmaf(id.x, ad, bb)), 0.f);
    r.y = fmaxf(fmaf(u.y, a2, fmaf(id.y, ad, bb)), 0.f);
    r.z = fmaxf(fmaf(u.z, a2, fmaf(id.z, ad, bb)), 0.f);
    r.w = fmaxf(fmaf(u.w, a2, fmaf(id.w, ad, bb)), 0.f);
    *(float4*)&out[base] = r;
}

// ---------------- side stream for conv_id overlap ---------------------------
namespace {
struct SideStream {
    cudaStream_t s2;
    cudaEvent_t ev_fork, ev_join;
    SideStream() {
        cudaStreamCreateWithFlags(&s2, cudaStreamNonBlocking);
        cudaEventCreateWithFlags(&ev_fork, cudaEventDisableTiming);
        cudaEventCreateWithFlags(&ev_join, cudaEventDisableTiming);
    }
};
SideStream g_ss;
}

// ---------------------------------------------------------------------------
extern "C" void kernel_launch(void* const* d_in, const int* in_sizes, int n_in,
                              void* d_out, int out_size) {
    const float* x     = (const float*)d_in[0];
    const float* f     = (const float*)d_in[1];
    const float* w_off = (const float*)d_in[2];
    const float* w_reg = (const float*)d_in[3];
    const float* g1    = (const float*)d_in[4];
    const float* b1    = (const float*)d_in[5];
    const float* w2    = (const float*)d_in[6];
    const float* g2    = (const float*)d_in[7];
    const float* b2    = (const float*)d_in[8];
    const float* wd    = (const float*)d_in[9];
    const float* gd    = (const float*)d_in[10];
    const float* bd    = (const float*)d_in[11];
    float* out = (float*)d_out;

    const int smem_deform = 12576 * 4;    // 50304 B (> 48K static limit)
    cudaFuncSetAttribute(deform_kernel,
        cudaFuncAttributeMaxDynamicSharedMemorySize, smem_deform);

    dim3 blk(32, 8);
    dim3 grd(WW / 32, HH / 8, DD);        // (5,16,32) offset/deform (P=1)
    dim3 grc(WW / 32, HH / 16, DD);       // (5, 8,32) conv3d (P=2 in y)
    dim3 ew4(HWSZ / 1024, DD, COUT_);     // (20,32,32) final, float4/thread

    // main stream: prerequisites for everything
    zero_stats_kernel<<<9, 256>>>();
    prep_weights_kernel<<<108, 256>>>(w2, wd, w_reg, w_off);

    // fork: conv_id depends only on x + prep/zero -> side stream
    cudaEventRecord(g_ss.ev_fork, 0);
    cudaStreamWaitEvent(g_ss.s2, g_ss.ev_fork, 0);
    conv3d_id_kernel<<<grc, blk, 0, g_ss.s2>>>(x);
    cudaEventRecord(g_ss.ev_join, g_ss.s2);

    // main stream: dependent chain
    offset_kernel<<<grd, blk>>>(f);
    deform_kernel<<<grd, blk, smem_deform>>>(x);
    bnstats1_kernel<<<4, 256>>>(g1, b1);
    conv3d_u_kernel<<<grc, blk>>>();      // BN1+ReLU fused into tile load

    // join: bnstats2/final need both conv outputs
    cudaStreamWaitEvent(0, g_ss.ev_join, 0);
    bnstats2_kernel<<<1, 64>>>(g2, b2, gd, bd);
    final_kernel<<<ew4, 256>>>(out);
}

// round 14
// speedup vs baseline: 1.9342x; 1.4572x over previous
#include <cuda_runtime.h>
#include <cuda_fp16.h>

#define DD   32
#define HH   128
#define WW   160
#define HWSZ (HH*WW)          // 20480
#define DHW  (DD*HWSZ)        // 655360
#define CIN_ 16
#define COUT_ 32

// ---------------- packed f32x2 helpers (Blackwell FFMA2 path) --------------
typedef unsigned long long u64t;

__device__ __forceinline__ u64t pack2(float a, float b) {
    u64t r;
    asm("mov.b64 %0, {%1, %2};" : "=l"(r) : "f"(a), "f"(b));
    return r;
}
__device__ __forceinline__ void fma2(u64t& d, u64t a, u64t b) {
    asm("fma.rn.f32x2 %0, %1, %2, %0;" : "+l"(d) : "l"(a), "l"(b));
}
__device__ __forceinline__ float2 unpack2(u64t v) {
    float2 r;
    asm("mov.b64 {%0, %1}, %2;" : "=f"(r.x), "=f"(r.y) : "l"(v));
    return r;
}

// ---------------- legacy tensor-core mma.sync (baseline PTX, sm_103-safe) --
__device__ __forceinline__ void mma16816(float* c,
                                         unsigned a0, unsigned a1,
                                         unsigned a2, unsigned a3,
                                         unsigned b0, unsigned b1) {
    asm volatile(
        "mma.sync.aligned.m16n8k16.row.col.f32.f16.f16.f32 "
        "{%0,%1,%2,%3}, {%4,%5,%6,%7}, {%8,%9}, {%0,%1,%2,%3};"
        : "+f"(c[0]), "+f"(c[1]), "+f"(c[2]), "+f"(c[3])
        : "r"(a0), "r"(a1), "r"(a2), "r"(a3), "r"(b0), "r"(b1));
}

// ---------------- scratch (allocation-free: device globals) ----------------
__device__ float g_off[18 * DHW];
__device__ float g_t1 [COUT_ * DHW];
__device__ float g_u  [COUT_ * DHW];
__device__ float g_id [COUT_ * DHW];
__device__ float g_s1sum[COUT_ * DD], g_s1sq[COUT_ * DD];
__device__ float g_s2sum[COUT_], g_s2sq[COUT_], g_sdsum[COUT_], g_sdsq[COUT_];
__device__ float g_a1[COUT_ * DD], g_b1f[COUT_ * DD];
__device__ float g_a2[COUT_], g_b2f[COUT_], g_ad[COUT_], g_bdf[COUT_];
__device__ float g_wrt[4608];            // [(c*9+k)*32 + o]
__device__ float g_wot[2592];            // [(c*9+k)*18 + j]
// fp16 conv weights [chunk][o=32][k=128] (k = cl*32 + t, t>=27 zero)
__device__ __align__(16) unsigned short g_w2h[8 * 4096];  // conv_u  (CI=32)
__device__ __align__(16) unsigned short g_wdh[4 * 4096];  // conv_id (CI=16)

// ---------------- kernel 0: zero stats -------------------------------------
__global__ void zero_stats_kernel() {
    int i = blockIdx.x * blockDim.x + threadIdx.x;
    if (i < COUT_ * DD) { g_s1sum[i] = 0.f; g_s1sq[i] = 0.f; }
    if (i < COUT_)      { g_s2sum[i] = 0.f; g_s2sq[i] = 0.f;
                          g_sdsum[i] = 0.f; g_sdsq[i] = 0.f; }
}

// ---------------- kernel 0b: weight prep -----------------------------------
__global__ void prep_weights_kernel(const float* __restrict__ w2,
                                    const float* __restrict__ wd,
                                    const float* __restrict__ w_reg,
                                    const float* __restrict__ w_off) {
    int i = blockIdx.x * blockDim.x + threadIdx.x;
    if (i < 8 * 4096) {                    // conv_u fp16 [chunk][o][k]
        int chunk = i >> 12, r = i & 4095, o = r >> 7, k = r & 127;
        int cg = chunk * 4 + (k >> 5), t = k & 31;
        float v = (t < 27) ? w2[(o * 32 + cg) * 27 + t] : 0.f;
        g_w2h[i] = __half_as_ushort(__float2half(v));
    }
    if (i < 4 * 4096) {                    // conv_id fp16
        int chunk = i >> 12, r = i & 4095, o = r >> 7, k = r & 127;
        int cg = chunk * 4 + (k >> 5), t = k & 31;
        float v = (t < 27) ? wd[(o * 16 + cg) * 27 + t] : 0.f;
        g_wdh[i] = __half_as_ushort(__float2half(v));
    }
    if (i < 4608) {
        int o = i & 31, ck = i >> 5;
        g_wrt[i] = w_reg[o * 144 + ck];
    }
    if (i < 2592) {
        int j = i % 18, ck = i / 18;
        g_wot[i] = w_off[j * 144 + ck];
    }
}

// ---------------- kernel 1: offset conv2d (R7, proven) ---------------------
__global__ void offset_kernel(const float* __restrict__ f) {
    __shared__ float sw[16 * 9 * 18];
    __shared__ float sf[16 * 10 * 34];
    const int tid = threadIdx.y * 32 + threadIdx.x;
    for (int i = tid; i < 648; i += 256)
        ((float4*)sw)[i] = ((const float4*)g_wot)[i];
    const int d = blockIdx.z, h0 = blockIdx.y * 8, w0 = blockIdx.x * 32;
    for (int i = tid; i < 16 * 340; i += 256) {
        int c = i / 340, r = i % 340, yy = r / 34, xx = r % 34;
        int hh = h0 + yy - 1, ww = w0 + xx - 1;
        float v = 0.f;
        if (hh >= 0 && hh < HH && ww >= 0 && ww < WW)
            v = f[c * DHW + d * HWSZ + hh * WW + ww];
        sf[i] = v;
    }
    __syncthreads();

    u64t off2[9];
#pragma unroll
    for (int j = 0; j < 9; j++) off2[j] = 0ull;
    const int ty = threadIdx.y, tx = threadIdx.x;
    for (int c = 0; c < 16; c++) {
#pragma unroll
        for (int ky = 0; ky < 3; ky++)
#pragma unroll
        for (int kx = 0; kx < 3; kx++) {
            float s = sf[c * 340 + (ty + ky) * 34 + (tx + kx)];
            u64t s2 = pack2(s, s);
            const u64t* wp = (const u64t*)&sw[(c * 9 + ky * 3 + kx) * 18];
#pragma unroll
            for (int j = 0; j < 9; j++) fma2(off2[j], s2, wp[j]);
        }
    }
    const int pix = d * HWSZ + (h0 + ty) * WW + (w0 + tx);
#pragma unroll
    for (int j = 0; j < 9; j++) {
        float2 p = unpack2(off2[j]);
        g_off[(2 * j    ) * DHW + pix] = fminf(1.f, fmaxf(-1.f, p.x));
        g_off[(2 * j + 1) * DHW + pix] = fminf(1.f, fmaxf(-1.f, p.y));
    }
}

// ---------------- kernel 2: deformable conv (R12, proven) ------------------
#define TROWS 13
#define TCOLS 38
#define TSZ   (TROWS * TCOLS)
__global__ void __launch_bounds__(256) deform_kernel(const float* __restrict__ x) {
    extern __shared__ float sm[];
    float* swr  = sm;
    float* sx   = sm + 4608;
    float* ssum = sm + 12512;
    float* ssq  = sm + 12544;

    const int tid = threadIdx.y * 32 + threadIdx.x;
    for (int i = tid; i < 1152; i += 256)
        ((float4*)swr)[i] = ((const float4*)g_wrt)[i];
    if (threadIdx.y == 0) { ssum[threadIdx.x] = 0.f; ssq[threadIdx.x] = 0.f; }

    const int d = blockIdx.z, h0 = blockIdx.y * 8, w0 = blockIdx.x * 32;
    const float* xd = x + d * HWSZ;

    for (int i = tid; i < 16 * TSZ; i += 256) {
        int c = i / TSZ, r = i % TSZ, yy = r / TCOLS, xx = r % TCOLS;
        int hh = h0 + yy - 2, ww = w0 + xx - 2;
        float v = 0.f;
        if (hh >= 0 && hh < HH && ww >= 0 && ww < WW)
            v = xd[c * DHW + hh * WW + ww];
        sx[i] = v;
    }
    __syncthreads();

    const int h = h0 + threadIdx.y;
    const int w = w0 + threadIdx.x;
    const int pix = d * HWSZ + h * WW + w;

    u64t acc2[16];
#pragma unroll
    for (int j = 0; j < 16; j++) acc2[j] = 0ull;

    for (int k = 0; k < 9; k++) {
        float dy = g_off[(2 * k    ) * DHW + pix];
        float dx = g_off[(2 * k + 1) * DHW + pix];
        float py = (float)(h - 1 + k / 3) + dy;
        float px = (float)(w - 1 + k % 3) + dx;
        float y0f = floorf(py), x0f = floorf(px);
        float wy = py - y0f, wx = px - x0f;
        int y0 = (int)y0f, x0 = (int)x0f, y1 = y0 + 1, x1 = x0 + 1;
        float my0 = (y0 >= 0 && y0 < HH) ? 1.f : 0.f;
        float my1 = (y1 >= 0 && y1 < HH) ? 1.f : 0.f;
        float mx0 = (x0 >= 0 && x0 < WW) ? 1.f : 0.f;
        float mx1 = (x1 >= 0 && x1 < WW) ? 1.f : 0.f;
        float w00 = (1.f - wy) * (1.f - wx) * my0 * mx0;
        float w01 = (1.f - wy) * wx         * my0 * mx1;
        float w10 = wy         * (1.f - wx) * my1 * mx0;
        float w11 = wy         * wx         * my1 * mx1;
        int ty0 = min(max(y0, 0), HH - 1) - h0 + 2;
        int ty1 = min(max(y1, 0), HH - 1) - h0 + 2;
        int tx0 = min(max(x0, 0), WW - 1) - w0 + 2;
        int tx1 = min(max(x1, 0), WW - 1) - w0 + 2;
        int o00 = ty0 * TCOLS + tx0, o01 = ty0 * TCOLS + tx1;
        int o10 = ty1 * TCOLS + tx0, o11 = ty1 * TCOLS + tx1;

#pragma unroll 4
        for (int c = 0; c < 16; c++) {
            const float* xc = sx + c * TSZ;
            float v = w00 * xc[o00] + w01 * xc[o01]
                    + w10 * xc[o10] + w11 * xc[o11];
            u64t v2 = pack2(v, v);
            const ulonglong2* wp = (const ulonglong2*)&swr[(c * 9 + k) * 32];
#pragma unroll
            for (int q = 0; q < 8; q++) {
                ulonglong2 t2 = wp[q];
                fma2(acc2[2 * q    ], v2, t2.x);
                fma2(acc2[2 * q + 1], v2, t2.y);
            }
        }
    }

    float av[32];
#pragma unroll
    for (int j = 0; j < 16; j++) {
        float2 p = unpack2(acc2[j]);
        av[2 * j] = p.x; av[2 * j + 1] = p.y;
    }
#pragma unroll
    for (int o = 0; o < 32; o++) g_t1[o * DHW + pix] = av[o];

#pragma unroll
    for (int o = 0; o < 32; o++) {
        float s = av[o], q = av[o] * av[o];
#pragma unroll
        for (int sh = 16; sh > 0; sh >>= 1) {
            s += __shfl_xor_sync(0xffffffffu, s, sh);
            q += __shfl_xor_sync(0xffffffffu, q, sh);
        }
        if (threadIdx.x == 0) { atomicAdd(&ssum[o], s); atomicAdd(&ssq[o], q); }
    }
    __syncthreads();
    if (threadIdx.y == 0) {
        atomicAdd(&g_s1sum[threadIdx.x * DD + d], ssum[threadIdx.x]);
        atomicAdd(&g_s1sq [threadIdx.x * DD + d], ssq [threadIdx.x]);
    }
}

// ---------------- kernel 3: fold BN1 stats ---------------------------------
__global__ void bnstats1_kernel(const float* __restrict__ g1,
                                const float* __restrict__ b1) {
    int i = blockIdx.x * blockDim.x + threadIdx.x;
    if (i < COUT_ * DD) {
        int o = i / DD;
        float n = (float)HWSZ;
        float m = g_s1sum[i] / n;
        float v = g_s1sq[i] / n - m * m;
        float a = g1[o] * rsqrtf(fmaxf(v, 0.f) + 1e-5f);
        g_a1[i] = a;
        g_b1f[i] = b1[o] - m * a;
    }
}

// ---------------- conv3d via legacy mma.sync fp16 ---------------------------
// Block = 128 threads (4 warps) = one (d, 4x32 px) tile. GEMM: M=128 pixels,
// N=32 outputs, K=128 per 4-ch chunk (27 taps zero-padded to 32 per channel).
// Per chunk: stage fp32 tile (+BN1 fuse) -> each thread writes its pixel's
// fp16 K-row to smem A[128][136] -> warps run m16n8k16 mma.sync
// (2m x 4n x 8k). Canonical fragment layout, direct LDS.32 loads.
#define ASTR 136            // half stride (padding kills bank conflicts)
template <int CI, bool FUSE_BN1>
__device__ __forceinline__ void conv3d_mma_body(const float* __restrict__ in,
                                                const unsigned short* __restrict__ wh,
                                                float* __restrict__ out,
                                                float* gsum, float* gsq) {
    extern __shared__ char smraw[];
    __half* As   = (__half*)smraw;                       // 128*136*2 = 34816 B
    __half* Bs   = (__half*)(smraw + 34816);             // 32*136*2  =  8704 B
    float*  tile = (float*)(smraw + 43520);              // 2448*4    =  9792 B
    float*  ssum = (float*)(smraw + 53312);              // 128 B
    float*  ssq  = ssum + 32;                            // total 53568 B

    const int tid  = threadIdx.x;
    const int wrp  = tid >> 5, lane = tid & 31;
    const int g    = lane >> 2, tg = lane & 3;
    const int d = blockIdx.z, h0 = blockIdx.y * 4, w0 = blockIdx.x * 32;
    const int py = tid >> 5, px_ = tid & 31;             // pixel = (py, px_)
    constexpr int NCH = CI / 4;

    if (tid < 32) { ssum[tid] = 0.f; ssq[tid] = 0.f; }

    float acc[32];                                        // [m][n][4]
#pragma unroll
    for (int j = 0; j < 32; j++) acc[j] = 0.f;

    for (int chunk = 0; chunk < NCH; chunk++) {
        __syncthreads();                                  // B reuse safe
        // stage fp32 tile: 4ch x 3dz x 6rows x 34cols (+BN1 fuse)
        for (int i = tid; i < 2448; i += 128) {
            int cl = i / 612, r = i % 612, dz = r / 204;
            int r2 = r % 204, yy = r2 / 34, xx = r2 % 34;
            int dd = d + dz - 1, hh = h0 + yy - 1, ww = w0 + xx - 1;
            float v = 0.f;
            if (dd >= 0 && dd < DD && hh >= 0 && hh < HH && ww >= 0 && ww < WW) {
                int cg = chunk * 4 + cl;
                v = in[cg * DHW + dd * HWSZ + hh * WW + ww];
                if (FUSE_BN1)
                    v = fmaxf(fmaf(v, g_a1[cg * DD + dd], g_b1f[cg * DD + dd]), 0.f);
            }
            tile[i] = v;
        }
        // stage B chunk: [o][k] fp16, row stride ASTR
        {
            const __half2* src = (const __half2*)wh + chunk * 2048;
            __half2* dst = (__half2*)Bs;
            for (int i = tid; i < 2048; i += 128) {
                int o = i >> 6, k2 = i & 63;
                dst[o * (ASTR / 2) + k2] = src[i];
            }
        }
        __syncthreads();

        // build this pixel's fp16 K-row: k = cl*32 + t (t<27 data, pad 0)
        {
            __half2* arow = (__half2*)(As + tid * ASTR);
            const __half2 z2 = __floats2half2_rn(0.f, 0.f);
#pragma unroll
            for (int cl = 0; cl < 4; cl++) {
                float v[28];
#pragma unroll
                for (int t = 0; t < 27; t++) {
                    int dz = t / 9, ky = (t / 3) % 3, kx = t % 3;
                    v[t] = tile[cl * 612 + dz * 204 + (py + ky) * 34 + (px_ + kx)];
                }
                v[27] = 0.f;
#pragma unroll
                for (int p = 0; p < 14; p++)
                    arow[cl * 16 + p] = __floats2half2_rn(v[2 * p], v[2 * p + 1]);
                arow[cl * 16 + 14] = z2;
                arow[cl * 16 + 15] = z2;
            }
        }
        __syncwarp();                                     // A rows warp-private

        // mma: 8 k-steps x (2 m-tiles x 4 n-tiles)
#pragma unroll
        for (int ks = 0; ks < 8; ks++) {
            const int k0 = ks * 16 + tg * 2;
            unsigned b0[4], b1[4];
#pragma unroll
            for (int n = 0; n < 4; n++) {
                const __half* bp = Bs + (n * 8 + g) * ASTR + k0;
                b0[n] = *(const unsigned*)bp;
                b1[n] = *(const unsigned*)(bp + 8);
            }
#pragma unroll
            for (int m = 0; m < 2; m++) {
                const __half* ap = As + (wrp * 32 + m * 16 + g) * ASTR + k0;
                unsigned a0 = *(const unsigned*)ap;
                unsigned a1 = *(const unsigned*)(ap + 8 * ASTR);
                unsigned a2 = *(const unsigned*)(ap + 8);
                unsigned a3 = *(const unsigned*)(ap + 8 * ASTR + 8);
#pragma unroll
                for (int n = 0; n < 4; n++)
                    mma16816(&acc[m * 16 + n * 4], a0, a1, a2, a3, b0[n], b1[n]);
            }
        }
    }

    // epilogue: park D fragments in smem (reuse A region), per-pixel readout
    __syncthreads();                                      // all mma reads done
    float* Dst = (float*)As;                              // [pixel][o], stride 33
#pragma unroll
    for (int m = 0; m < 2; m++) {
        int r0 = wrp * 32 + m * 16 + g;
#pragma unroll
        for (int n = 0; n < 4; n++) {
            int c0 = n * 8 + tg * 2;
            Dst[r0 * 33 + c0]           = acc[m * 16 + n * 4 + 0];
            Dst[r0 * 33 + c0 + 1]       = acc[m * 16 + n * 4 + 1];
            Dst[(r0 + 8) * 33 + c0]     = acc[m * 16 + n * 4 + 2];
            Dst[(r0 + 8) * 33 + c0 + 1] = acc[m * 16 + n * 4 + 3];
        }
    }
    __syncwarp();                                         // Dst rows warp-private

    const int pix = d * HWSZ + (h0 + py) * WW + (w0 + px_);
#pragma unroll
    for (int o = 0; o < 32; o++) {
        float vv = Dst[tid * 33 + o];
        out[o * DHW + pix] = vv;
        float s = vv, q = vv * vv;
#pragma unroll
        for (int sh = 16; sh > 0; sh >>= 1) {
            s += __shfl_xor_sync(0xffffffffu, s, sh);
            q += __shfl_xor_sync(0xffffffffu, q, sh);
        }
        if (lane == 0) { atomicAdd(&ssum[o], s); atomicAdd(&ssq[o], q); }
    }
    __syncthreads();
    if (tid < 32) {
        atomicAdd(&gsum[tid], ssum[tid]);
        atomicAdd(&gsq [tid], ssq [tid]);
    }
}

__global__ void __launch_bounds__(128) conv3d_u_kernel() {
    conv3d_mma_body<32, true>(g_t1, g_w2h, g_u, g_s2sum, g_s2sq);
}
__global__ void __launch_bounds__(128) conv3d_id_kernel(const float* __restrict__ x) {
    conv3d_mma_body<16, false>(x, g_wdh, g_id, g_sdsum, g_sdsq);
}

// ---------------- kernel 5: fold BN2 / BNd stats ----------------------------
__global__ void bnstats2_kernel(const float* __restrict__ g2,
                                const float* __restrict__ b2,
                                const float* __restrict__ gd,
                                const float* __restrict__ bd) {
    int i = threadIdx.x;
    float n = (float)DHW;
    if (i < 32) {
        float m = g_s2sum[i] / n;
        float v = g_s2sq[i] / n - m * m;
        float a = g2[i] * rsqrtf(fmaxf(v, 0.f) + 1e-5f);
        g_a2[i] = a; g_b2f[i] = b2[i] - m * a;
    } else if (i < 64) {
        int o = i - 32;
        float m = g_sdsum[o] / n;
        float v = g_sdsq[o] / n - m * m;
        float a = gd[o] * rsqrtf(fmaxf(v, 0.f) + 1e-5f);
        g_ad[o] = a; g_bdf[o] = bd[o] - m * a;
    }
}

// ---------------- kernel 6: out = relu(bn(u) + bn(id)), float4 --------------
__global__ void final_kernel(float* __restrict__ out) {
    int o = blockIdx.z, d = blockIdx.y;
    int base = o * DHW + d * HWSZ + (blockIdx.x * 256 + threadIdx.x) * 4;
    float4 u  = *(const float4*)&g_u[base];
    float4 id = *(const float4*)&g_id[base];
    float a2 = g_a2[o], ad = g_ad[o];
    float bb = g_b2f[o] + g_bdf[o];
    float4 r;
    r.x = fmaxf(fmaf(u.x, a2, fmaf(id.x, ad, bb)), 0.f);
    r.y = fmaxf(fmaf(u.y, a2, fmaf(id.y, ad, bb)), 0.f);
    r.z = fmaxf(fmaf(u.z, a2, fmaf(id.z, ad, bb)), 0.f);
    r.w = fmaxf(fmaf(u.w, a2, fmaf(id.w, ad, bb)), 0.f);
    *(float4*)&out[base] = r;
}

// ---------------- side stream for conv_id overlap ----------------------------
namespace {
struct SideStream {
    cudaStream_t s2;
    cudaEvent_t ev_fork, ev_join;
    SideStream() {
        cudaStreamCreateWithFlags(&s2, cudaStreamNonBlocking);
        cudaEventCreateWithFlags(&ev_fork, cudaEventDisableTiming);
        cudaEventCreateWithFlags(&ev_join, cudaEventDisableTiming);
    }
};
SideStream g_ss;
}

// ---------------------------------------------------------------------------
extern "C" void kernel_launch(void* const* d_in, const int* in_sizes, int n_in,
                              void* d_out, int out_size) {
    const float* x     = (const float*)d_in[0];
    const float* f     = (const float*)d_in[1];
    const float* w_off = (const float*)d_in[2];
    const float* w_reg = (const float*)d_in[3];
    const float* g1    = (const float*)d_in[4];
    const float* b1    = (const float*)d_in[5];
    const float* w2    = (const float*)d_in[6];
    const float* g2    = (const float*)d_in[7];
    const float* b2    = (const float*)d_in[8];
    const float* wd    = (const float*)d_in[9];
    const float* gd    = (const float*)d_in[10];
    const float* bd    = (const float*)d_in[11];
    float* out = (float*)d_out;

    const int smem_deform = 12576 * 4;    // 50304 B
    const int smem_conv   = 53568;        // A+B+tile+stats
    cudaFuncSetAttribute(deform_kernel,
        cudaFuncAttributeMaxDynamicSharedMemorySize, smem_deform);
    cudaFuncSetAttribute(conv3d_u_kernel,
        cudaFuncAttributeMaxDynamicSharedMemorySize, smem_conv);
    cudaFuncSetAttribute(conv3d_id_kernel,
        cudaFuncAttributeMaxDynamicSharedMemorySize, smem_conv);

    dim3 blk(32, 8);
    dim3 grd(WW / 32, HH / 8, DD);        // (5,16,32) offset/deform
    dim3 grt(WW / 32, HH / 4, DD);        // (5,32,32) mma conv, 128 thr
    dim3 ew4(HWSZ / 1024, DD, COUT_);     // (20,32,32) final

    zero_stats_kernel<<<9, 256>>>();
    prep_weights_kernel<<<128, 256>>>(w2, wd, w_reg, w_off);

    // fork: conv_id (tensor) on side stream
    cudaEventRecord(g_ss.ev_fork, 0);
    cudaStreamWaitEvent(g_ss.s2, g_ss.ev_fork, 0);
    conv3d_id_kernel<<<grt, 128, smem_conv, g_ss.s2>>>(x);
    cudaEventRecord(g_ss.ev_join, g_ss.s2);

    // main stream: dependent chain
    offset_kernel<<<grd, blk>>>(f);
    deform_kernel<<<grd, blk, smem_deform>>>(x);
    bnstats1_kernel<<<4, 256>>>(g1, b1);
    conv3d_u_kernel<<<grt, 128, smem_conv>>>();   // BN1+ReLU fused in staging

    cudaStreamWaitEvent(0, g_ss.ev_join, 0);
    bnstats2_kernel<<<1, 64>>>(g2, b2, gd, bd);
    final_kernel<<<ew4, 256>>>(out);
}